// round 7
// baseline (speedup 1.0000x reference)
#include <cuda_runtime.h>
#include <cuda_fp16.h>
#include <cstdint>

#define B_ 2
#define L_ 64
#define D_ 1024
#define H_ 512
#define S_ 50000
#define V_ 40000
#define KDEG 32
#define R_ 128
#define BN_EPS 1e-5f
#define SLM_SCALE 0.1f

// ---- scratch (device globals; no allocation allowed) ----
__device__ float g_scale[L_];
__device__ float g_shift[L_];
__device__ __half g_h_hi[R_ * H_];
__device__ __half g_h_lo[R_ * H_];
__device__ __half g_vT[(size_t)V_ * R_];   // transposed v (fp16): [V][128]

// ============================================================
// helpers
// ============================================================
__device__ __forceinline__ uint32_t smem_u32(const void* p) {
    uint32_t a;
    asm("{ .reg .u64 t; cvta.to.shared.u64 t, %1; cvt.u32.u64 %0, t; }" : "=r"(a) : "l"(p));
    return a;
}
__device__ __forceinline__ void ldsm_x4(uint32_t* r, uint32_t addr) {
    asm volatile("ldmatrix.sync.aligned.m8n8.x4.shared.b16 {%0,%1,%2,%3}, [%4];"
        : "=r"(r[0]), "=r"(r[1]), "=r"(r[2]), "=r"(r[3]) : "r"(addr));
}
__device__ __forceinline__ void ldsm_x4_t(uint32_t* r, uint32_t addr) {
    asm volatile("ldmatrix.sync.aligned.m8n8.x4.trans.shared.b16 {%0,%1,%2,%3}, [%4];"
        : "=r"(r[0]), "=r"(r[1]), "=r"(r[2]), "=r"(r[3]) : "r"(addr));
}
__device__ __forceinline__ void mma16816(float* c, const uint32_t* a, const uint32_t* b) {
    asm volatile("mma.sync.aligned.m16n8k16.row.col.f32.f16.f16.f32 "
        "{%0,%1,%2,%3}, {%4,%5,%6,%7}, {%8,%9}, {%0,%1,%2,%3};"
        : "+f"(c[0]), "+f"(c[1]), "+f"(c[2]), "+f"(c[3])
        : "r"(a[0]), "r"(a[1]), "r"(a[2]), "r"(a[3]), "r"(b[0]), "r"(b[1]));
}
__device__ __forceinline__ uint32_t pack_h2(float x, float y) {
    __half2 h = __floats2half2_rn(x, y);
    return *reinterpret_cast<uint32_t*>(&h);
}

// ============================================================
// Kernel 1: BatchNorm stats
// ============================================================
__global__ void bn_stats_kernel(const float* __restrict__ x,
                                const float* __restrict__ gamma,
                                const float* __restrict__ beta) {
    int l = blockIdx.x;
    int t = threadIdx.x;
    float s = 0.f, sq = 0.f;
    for (int b = 0; b < B_; b++) {
        const float* row = x + ((size_t)(b * L_ + l)) * D_;
        for (int d = t; d < D_; d += 256) {
            float v = row[d];
            s += v; sq += v * v;
        }
    }
    __shared__ float sh_s[256], sh_q[256];
    sh_s[t] = s; sh_q[t] = sq;
    __syncthreads();
    for (int off = 128; off > 0; off >>= 1) {
        if (t < off) { sh_s[t] += sh_s[t + off]; sh_q[t] += sh_q[t + off]; }
        __syncthreads();
    }
    if (t == 0) {
        float inv = 1.f / (float)(B_ * D_);
        float mean = sh_s[0] * inv;
        float var = sh_q[0] * inv - mean * mean;
        float sc = gamma[l] * rsqrtf(var + BN_EPS);
        g_scale[l] = sc;
        g_shift[l] = beta[l] - mean * sc;
    }
}

// ============================================================
// Kernel 2: h = relu(BN(x)@W1+b1), emitted as split fp16 (hi/lo)
// ============================================================
__global__ void h_kernel(const float* __restrict__ A,
                         const float* __restrict__ W,
                         const float* __restrict__ bias) {
    constexpr int K = D_, N = H_;
    constexpr int BK = 16, TM = 8, TN = 4;
    __shared__ float As[BK][128];
    __shared__ float Bs[BK][64];

    const int tid = threadIdx.x;
    const int n0 = blockIdx.x * 64;
    const int trow = tid & 15;
    const int tcol = tid >> 4;
    const int kq = tid & 3;
    const int mA = tid >> 2;
    const int nq = tid & 15;
    const int kB = tid >> 4;

    float acc[TM][TN];
#pragma unroll
    for (int i = 0; i < TM; i++)
#pragma unroll
        for (int j = 0; j < TN; j++) acc[i][j] = 0.f;

    for (int k0 = 0; k0 < K; k0 += BK) {
#pragma unroll
        for (int mm = 0; mm < 2; mm++) {
            int m = mA + mm * 64;
            float4 a = *(const float4*)(A + (size_t)m * K + k0 + kq * 4);
            float sc = g_scale[m & (L_ - 1)];
            float sh = g_shift[m & (L_ - 1)];
            a.x = fmaf(a.x, sc, sh); a.y = fmaf(a.y, sc, sh);
            a.z = fmaf(a.z, sc, sh); a.w = fmaf(a.w, sc, sh);
            As[kq * 4 + 0][m] = a.x; As[kq * 4 + 1][m] = a.y;
            As[kq * 4 + 2][m] = a.z; As[kq * 4 + 3][m] = a.w;
        }
        {
            int n = n0 + nq * 4;
            float4 b = *(const float4*)(W + (size_t)(k0 + kB) * N + n);
            *(float4*)&Bs[kB][nq * 4] = b;
        }
        __syncthreads();
#pragma unroll
        for (int k = 0; k < BK; k++) {
            float a[TM], bb[TN];
#pragma unroll
            for (int i = 0; i < TM; i++) a[i] = As[k][trow * TM + i];
#pragma unroll
            for (int j = 0; j < TN; j++) bb[j] = Bs[k][tcol * TN + j];
#pragma unroll
            for (int i = 0; i < TM; i++)
#pragma unroll
                for (int j = 0; j < TN; j++) acc[i][j] = fmaf(a[i], bb[j], acc[i][j]);
        }
        __syncthreads();
    }

#pragma unroll
    for (int j = 0; j < TN; j++) {
        int n = n0 + tcol * TN + j;
        float bz = bias[n];
#pragma unroll
        for (int i = 0; i < TM; i++) {
            int m = trow * TM + i;
            float val = fmaxf(acc[i][j] + bz, 0.f);
            __half hi = __float2half_rn(val);
            g_h_hi[(size_t)m * H_ + n] = hi;
            g_h_lo[(size_t)m * H_ + n] = __float2half_rn(val - __half2float(hi));
        }
    }
}

// ============================================================
// Kernel 3: fp16 mma.sync GEMM  C[128,N] = h[128,512]@W[512,N] + bias
// MODE 1: 2-pass (A hi+lo), epilogue = y + fused sparse gather -> out fp32
// MODE 2: 1-pass (A hi),     epilogue = vT fp16 transposed [N][128]
// CTA: 256 threads (8 warps, 2M x 4N), tile 128x128, K chunks of 64.
// ============================================================
#define A_HI 0
#define A_LO 16384
#define B_OFF 32768
#define GEMM_SMEM 67584   // epilogue fp32 tile 128*132*4 dominates

template <int MODE>
__global__ void __launch_bounds__(256, 2)
mma_gemm(const float* __restrict__ W, const float* __restrict__ bias,
         float* __restrict__ outparam, int N,
         const int* __restrict__ sl_idx, const float* __restrict__ sl_w) {
    extern __shared__ char smem[];
    const uint32_t sb = smem_u32(smem);
    const int tid = threadIdx.x;
    const int lane = tid & 31;
    const int wid = tid >> 5;
    const int wm = wid >> 2;         // 0..1
    const int wn = wid & 3;          // 0..3
    const int n0 = blockIdx.x * 128;

    const int tt = lane >> 3;        // ldmatrix tile group 0..3
    const int lr = lane & 7;
    const uint32_t swz = (uint32_t)lr << 4;

    float c[4][4][4];
#pragma unroll
    for (int a = 0; a < 4; a++)
#pragma unroll
        for (int b = 0; b < 4; b++)
#pragma unroll
            for (int d = 0; d < 4; d++) c[a][b][d] = 0.f;

    for (int ch = 0; ch < 8; ch++) {
        const int k0 = ch * 64;

        // ---- fill A: [128 m][64 k] fp16, swizzled 128B rows (hi, + lo in MODE 1)
#pragma unroll
        for (int i = 0; i < 4; i++) {
            int idx = i * 256 + tid;
            int m = idx >> 3, q = idx & 7;
            uint32_t off = (uint32_t)(m * 128 + ((q * 16) ^ ((m & 7) << 4)));
            *(uint4*)(smem + A_HI + off) = *(const uint4*)(g_h_hi + (size_t)m * H_ + k0 + q * 8);
            if (MODE == 1)
                *(uint4*)(smem + A_LO + off) = *(const uint4*)(g_h_lo + (size_t)m * H_ + k0 + q * 8);
        }
        // ---- fill B: [64 k][128 n] fp16, rows 256B, swizzle ((k&7)<<4)
#pragma unroll
        for (int i = 0; i < 8; i++) {
            int k = (tid >> 5) + i * 8;
            int nl = (tid & 31) * 4;
            int gn = n0 + nl;
            float4 w4 = make_float4(0.f, 0.f, 0.f, 0.f);
            if (gn < N) w4 = *(const float4*)(W + (size_t)(k0 + k) * N + gn);
            uint32_t off = (uint32_t)(k * 256 + ((nl * 2) ^ ((k & 7) << 4)));
            uint2 hv;
            hv.x = pack_h2(w4.x, w4.y); hv.y = pack_h2(w4.z, w4.w);
            *(uint2*)(smem + B_OFF + off) = hv;
        }
        __syncthreads();

        // ---- consume: 4 k-steps of 16
#pragma unroll
        for (int ks = 0; ks < 4; ks++) {
            uint32_t bh[2][4];
#pragma unroll
            for (int nt = 0; nt < 2; nt++) {
                uint32_t boff = (uint32_t)((ks * 16 + (tt & 1) * 8 + lr) * 256 +
                                ((wn * 64 + nt * 32 + (tt >> 1) * 16) ^ swz));
                ldsm_x4_t(bh[nt], sb + B_OFF + boff);
            }
#pragma unroll
            for (int mt = 0; mt < 4; mt++) {
                uint32_t ah[4], al[4];
                uint32_t aoff = (uint32_t)((wm * 64 + mt * 16 + (tt & 1) * 8 + lr) * 128 +
                                ((ks * 32 + (tt >> 1) * 16) ^ swz));
                ldsm_x4(ah, sb + A_HI + aoff);
                if (MODE == 1) ldsm_x4(al, sb + A_LO + aoff);
#pragma unroll
                for (int nt = 0; nt < 2; nt++) {
#pragma unroll
                    for (int f = 0; f < 2; f++) {
                        float* cc = c[mt][nt * 2 + f];
                        mma16816(cc, ah, &bh[nt][2 * f]);
                        if (MODE == 1) mma16816(cc, al, &bh[nt][2 * f]);
                    }
                }
            }
        }
        __syncthreads();
    }

    // ---- epilogue: stage fp32 tile [128 m][132] with bias ----
    float* sf = (float*)smem;
#pragma unroll
    for (int mt = 0; mt < 4; mt++) {
        int m = wm * 64 + mt * 16 + (lane >> 2);
#pragma unroll
        for (int nt = 0; nt < 4; nt++) {
            int nl = wn * 32 + nt * 8 + 2 * (lane & 3);
            int gn = n0 + nl;
            float b0 = (gn < N) ? __ldg(bias + gn) : 0.f;
            float b1 = (gn + 1 < N) ? __ldg(bias + gn + 1) : 0.f;
            *(float2*)(sf + m * 132 + nl) = make_float2(c[mt][nt][0] + b0, c[mt][nt][1] + b1);
            *(float2*)(sf + (m + 8) * 132 + nl) = make_float2(c[mt][nt][2] + b0, c[mt][nt][3] + b1);
        }
    }
    __syncthreads();

    if (MODE == 1) {
        // fused sparse gather: each warp owns 16 s-columns of the tile
        for (int sl = wid * 16; sl < wid * 16 + 16; sl++) {
            int s = n0 + sl;
            if (s >= N) break;
            float4 acc = make_float4(0.f, 0.f, 0.f, 0.f);
#pragma unroll 8
            for (int k = 0; k < KDEG; k++) {
                int jj = __ldg(sl_idx + (size_t)s * KDEG + k);
                float wk = __ldg(sl_w + (size_t)s * KDEG + k);
                uint2 raw = *(const uint2*)(g_vT + (size_t)jj * R_ + lane * 4);
                __half2 p0 = *reinterpret_cast<__half2*>(&raw.x);
                __half2 p1 = *reinterpret_cast<__half2*>(&raw.y);
                float2 f0 = __half22float2(p0);
                float2 f1 = __half22float2(p1);
                acc.x = fmaf(wk, f0.x, acc.x);
                acc.y = fmaf(wk, f0.y, acc.y);
                acc.z = fmaf(wk, f1.x, acc.z);
                acc.w = fmaf(wk, f1.y, acc.w);
            }
            sf[(lane * 4 + 0) * 132 + sl] += SLM_SCALE * acc.x;
            sf[(lane * 4 + 1) * 132 + sl] += SLM_SCALE * acc.y;
            sf[(lane * 4 + 2) * 132 + sl] += SLM_SCALE * acc.z;
            sf[(lane * 4 + 3) * 132 + sl] += SLM_SCALE * acc.w;
        }
        __syncthreads();
        // coalesced store
        float* out = outparam;
        for (int idx = tid; idx < 128 * 128; idx += 256) {
            int m = idx >> 7, n = idx & 127;
            int gn = n0 + n;
            if (gn < N) out[(size_t)m * N + gn] = sf[m * 132 + n];
        }
    } else {
        // write transposed fp16 rows coalesced: vT[n][m]
        for (int idx = tid; idx < 128 * 64; idx += 256) {
            int n = idx >> 6, mp = idx & 63;
            int gn = n0 + n;
            if (gn < N) {
                float v0 = sf[(2 * mp) * 132 + n];
                float v1 = sf[(2 * mp + 1) * 132 + n];
                uint32_t packed = pack_h2(v0, v1);
                *(uint32_t*)((char*)g_vT + ((size_t)gn * R_ + 2 * mp) * 2) = packed;
            }
        }
    }
}

// ============================================================
extern "C" void kernel_launch(void* const* d_in, const int* in_sizes, int n_in,
                              void* d_out, int out_size) {
    const float* x     = (const float*)d_in[0];
    const float* gamma = (const float*)d_in[1];
    const float* beta  = (const float*)d_in[2];
    const float* W1    = (const float*)d_in[3];
    const float* b1    = (const float*)d_in[4];
    const float* W2    = (const float*)d_in[5];
    const float* b2    = (const float*)d_in[6];
    const float* Wslm  = (const float*)d_in[7];
    const float* bslm  = (const float*)d_in[8];
    const float* slw   = (const float*)d_in[9];
    const int*   slidx = (const int*)d_in[10];
    float* out = (float*)d_out;

    cudaFuncSetAttribute(mma_gemm<1>, cudaFuncAttributeMaxDynamicSharedMemorySize, GEMM_SMEM);
    cudaFuncSetAttribute(mma_gemm<2>, cudaFuncAttributeMaxDynamicSharedMemorySize, GEMM_SMEM);

    bn_stats_kernel<<<L_, 256>>>(x, gamma, beta);
    h_kernel<<<H_ / 64, 256>>>(x, W1, b1);
    // v first (gather input), then y with fused gather
    mma_gemm<2><<<(V_ + 127) / 128, 256, GEMM_SMEM>>>(Wslm, bslm, nullptr, V_, nullptr, nullptr);
    mma_gemm<1><<<(S_ + 127) / 128, 256, GEMM_SMEM>>>(W2, b2, out, S_, slidx, slw);
}

// round 8
// speedup vs baseline: 1.3395x; 1.3395x over previous
#include <cuda_runtime.h>
#include <cuda_bf16.h>
#include <cstdint>

#define B_ 2
#define L_ 64
#define D_ 1024
#define H_ 512
#define S_ 50000
#define V_ 40000
#define KDEG 32
#define R_ 128
#define BN_EPS 1e-5f
#define SLM_SCALE 0.1f

// ---- scratch (device globals; no allocation allowed) ----
__device__ float g_scale[L_];
__device__ float g_shift[L_];
__device__ __nv_bfloat16 g_h_hi[R_ * H_];
__device__ __nv_bfloat16 g_h_lo[R_ * H_];
__device__ __nv_bfloat16 g_vT[(size_t)V_ * R_];   // transposed v (bf16): [V][128]

// ============================================================
// helpers
// ============================================================
__device__ __forceinline__ uint32_t smem_u32(const void* p) {
    uint32_t a;
    asm("{ .reg .u64 t; cvta.to.shared.u64 t, %1; cvt.u32.u64 %0, t; }" : "=r"(a) : "l"(p));
    return a;
}
__device__ __forceinline__ void ldsm_x4(uint32_t* r, uint32_t addr) {
    asm volatile("ldmatrix.sync.aligned.m8n8.x4.shared.b16 {%0,%1,%2,%3}, [%4];"
        : "=r"(r[0]), "=r"(r[1]), "=r"(r[2]), "=r"(r[3]) : "r"(addr));
}
__device__ __forceinline__ void ldsm_x4_t(uint32_t* r, uint32_t addr) {
    asm volatile("ldmatrix.sync.aligned.m8n8.x4.trans.shared.b16 {%0,%1,%2,%3}, [%4];"
        : "=r"(r[0]), "=r"(r[1]), "=r"(r[2]), "=r"(r[3]) : "r"(addr));
}
__device__ __forceinline__ void mma16816(float* c, const uint32_t* a, const uint32_t* b) {
    asm volatile("mma.sync.aligned.m16n8k16.row.col.f32.bf16.bf16.f32 "
        "{%0,%1,%2,%3}, {%4,%5,%6,%7}, {%8,%9}, {%0,%1,%2,%3};"
        : "+f"(c[0]), "+f"(c[1]), "+f"(c[2]), "+f"(c[3])
        : "r"(a[0]), "r"(a[1]), "r"(a[2]), "r"(a[3]), "r"(b[0]), "r"(b[1]));
}
__device__ __forceinline__ uint32_t pack_hi2(float x, float y) {
    __nv_bfloat16 hx = __float2bfloat16(x), hy = __float2bfloat16(y);
    return (uint32_t)__bfloat16_as_ushort(hx) | ((uint32_t)__bfloat16_as_ushort(hy) << 16);
}
__device__ __forceinline__ uint32_t pack_lo2(float x, float y) {
    __nv_bfloat16 hx = __float2bfloat16(x), hy = __float2bfloat16(y);
    __nv_bfloat16 lx = __float2bfloat16(x - __bfloat162float(hx));
    __nv_bfloat16 ly = __float2bfloat16(y - __bfloat162float(hy));
    return (uint32_t)__bfloat16_as_ushort(lx) | ((uint32_t)__bfloat16_as_ushort(ly) << 16);
}

// ============================================================
// Kernel 1: BatchNorm stats
// ============================================================
__global__ void bn_stats_kernel(const float* __restrict__ x,
                                const float* __restrict__ gamma,
                                const float* __restrict__ beta) {
    int l = blockIdx.x;
    int t = threadIdx.x;
    float s = 0.f, sq = 0.f;
    for (int b = 0; b < B_; b++) {
        const float* row = x + ((size_t)(b * L_ + l)) * D_;
        for (int d = t; d < D_; d += 256) {
            float v = row[d];
            s += v; sq += v * v;
        }
    }
    __shared__ float sh_s[256], sh_q[256];
    sh_s[t] = s; sh_q[t] = sq;
    __syncthreads();
    for (int off = 128; off > 0; off >>= 1) {
        if (t < off) { sh_s[t] += sh_s[t + off]; sh_q[t] += sh_q[t + off]; }
        __syncthreads();
    }
    if (t == 0) {
        float inv = 1.f / (float)(B_ * D_);
        float mean = sh_s[0] * inv;
        float var = sh_q[0] * inv - mean * mean;
        float sc = gamma[l] * rsqrtf(var + BN_EPS);
        g_scale[l] = sc;
        g_shift[l] = beta[l] - mean * sc;
    }
}

// ============================================================
// Kernel 2: h = relu(BN(x)@W1+b1), emitted as split bf16 (hi/lo)
// ============================================================
__global__ void h_kernel(const float* __restrict__ A,
                         const float* __restrict__ W,
                         const float* __restrict__ bias) {
    constexpr int K = D_, N = H_;
    constexpr int BK = 16, TM = 8, TN = 4;
    __shared__ float As[BK][128];
    __shared__ float Bs[BK][64];

    const int tid = threadIdx.x;
    const int n0 = blockIdx.x * 64;
    const int trow = tid & 15;
    const int tcol = tid >> 4;
    const int kq = tid & 3;
    const int mA = tid >> 2;
    const int nq = tid & 15;
    const int kB = tid >> 4;

    float acc[TM][TN];
#pragma unroll
    for (int i = 0; i < TM; i++)
#pragma unroll
        for (int j = 0; j < TN; j++) acc[i][j] = 0.f;

    for (int k0 = 0; k0 < K; k0 += BK) {
#pragma unroll
        for (int mm = 0; mm < 2; mm++) {
            int m = mA + mm * 64;
            float4 a = *(const float4*)(A + (size_t)m * K + k0 + kq * 4);
            float sc = g_scale[m & (L_ - 1)];
            float sh = g_shift[m & (L_ - 1)];
            a.x = fmaf(a.x, sc, sh); a.y = fmaf(a.y, sc, sh);
            a.z = fmaf(a.z, sc, sh); a.w = fmaf(a.w, sc, sh);
            As[kq * 4 + 0][m] = a.x; As[kq * 4 + 1][m] = a.y;
            As[kq * 4 + 2][m] = a.z; As[kq * 4 + 3][m] = a.w;
        }
        {
            int n = n0 + nq * 4;
            float4 b = *(const float4*)(W + (size_t)(k0 + kB) * N + n);
            *(float4*)&Bs[kB][nq * 4] = b;
        }
        __syncthreads();
#pragma unroll
        for (int k = 0; k < BK; k++) {
            float a[TM], bb[TN];
#pragma unroll
            for (int i = 0; i < TM; i++) a[i] = As[k][trow * TM + i];
#pragma unroll
            for (int j = 0; j < TN; j++) bb[j] = Bs[k][tcol * TN + j];
#pragma unroll
            for (int i = 0; i < TM; i++)
#pragma unroll
                for (int j = 0; j < TN; j++) acc[i][j] = fmaf(a[i], bb[j], acc[i][j]);
        }
        __syncthreads();
    }

#pragma unroll
    for (int j = 0; j < TN; j++) {
        int n = n0 + tcol * TN + j;
        float bz = bias[n];
#pragma unroll
        for (int i = 0; i < TM; i++) {
            int m = trow * TM + i;
            float val = fmaxf(acc[i][j] + bz, 0.f);
            __nv_bfloat16 hi = __float2bfloat16(val);
            g_h_hi[(size_t)m * H_ + n] = hi;
            g_h_lo[(size_t)m * H_ + n] = __float2bfloat16(val - __bfloat162float(hi));
        }
    }
}

// ============================================================
// Kernel 3: split-bf16 mma.sync GEMM  C[128,N] = h[128,512]@W[512,N] + bias
// MODE 1: 3-pass (hiA*hiB + hiA*loB + loA*hiB), out row-major fp32 (y)
// MODE 2: 2-pass (hiA*hiB + loA*hiB, B_LO dropped), out = g_vT bf16 [N][128]
// CTA: 256 threads (8 warps, 2M x 4N), tile 128x128, K chunks of 64.
// ============================================================
#define A_HI 0
#define A_LO 16384
#define B_HI 32768
#define B_LO 49152
#define GEMM_SMEM 67584   // max(stage 64KB, epilogue 128*132*4)

template <int MODE>
__global__ void __launch_bounds__(256, 2)
mma_gemm(const float* __restrict__ W, const float* __restrict__ bias,
         float* __restrict__ outparam, int N) {
    extern __shared__ char smem[];
    const uint32_t sb = smem_u32(smem);
    const int tid = threadIdx.x;
    const int lane = tid & 31;
    const int wid = tid >> 5;
    const int wm = wid >> 2;         // 0..1
    const int wn = wid & 3;          // 0..3
    const int n0 = blockIdx.x * 128;

    const int tt = lane >> 3;        // ldmatrix tile group 0..3
    const int lr = lane & 7;
    const uint32_t swz = (uint32_t)lr << 4;

    float c[4][4][4];
#pragma unroll
    for (int a = 0; a < 4; a++)
#pragma unroll
        for (int b = 0; b < 4; b++)
#pragma unroll
            for (int d = 0; d < 4; d++) c[a][b][d] = 0.f;

    for (int ch = 0; ch < 8; ch++) {
        const int k0 = ch * 64;

        // ---- fill A: [128 m][64 k] bf16 hi/lo, swizzled 128B rows
#pragma unroll
        for (int i = 0; i < 4; i++) {
            int idx = i * 256 + tid;
            int m = idx >> 3, q = idx & 7;
            uint32_t off = (uint32_t)(m * 128 + ((q * 16) ^ ((m & 7) << 4)));
            *(uint4*)(smem + A_HI + off) = *(const uint4*)(g_h_hi + (size_t)m * H_ + k0 + q * 8);
            *(uint4*)(smem + A_LO + off) = *(const uint4*)(g_h_lo + (size_t)m * H_ + k0 + q * 8);
        }
        // ---- fill B: [64 k][128 n] bf16 hi (+lo in MODE 1), rows 256B
#pragma unroll
        for (int i = 0; i < 8; i++) {
            int k = (tid >> 5) + i * 8;
            int nl = (tid & 31) * 4;
            int gn = n0 + nl;
            float4 w4 = make_float4(0.f, 0.f, 0.f, 0.f);
            if (gn < N) w4 = *(const float4*)(W + (size_t)(k0 + k) * N + gn);
            uint32_t off = (uint32_t)(k * 256 + ((nl * 2) ^ ((k & 7) << 4)));
            uint2 hv;
            hv.x = pack_hi2(w4.x, w4.y); hv.y = pack_hi2(w4.z, w4.w);
            *(uint2*)(smem + B_HI + off) = hv;
            if (MODE == 1) {
                uint2 lv;
                lv.x = pack_lo2(w4.x, w4.y); lv.y = pack_lo2(w4.z, w4.w);
                *(uint2*)(smem + B_LO + off) = lv;
            }
        }
        __syncthreads();

        // ---- consume: 4 k-steps of 16
#pragma unroll
        for (int ks = 0; ks < 4; ks++) {
            uint32_t bh[2][4], bl[2][4];
#pragma unroll
            for (int nt = 0; nt < 2; nt++) {
                uint32_t boff = (uint32_t)((ks * 16 + (tt & 1) * 8 + lr) * 256 +
                                ((wn * 64 + nt * 32 + (tt >> 1) * 16) ^ swz));
                ldsm_x4_t(bh[nt], sb + B_HI + boff);
                if (MODE == 1) ldsm_x4_t(bl[nt], sb + B_LO + boff);
            }
#pragma unroll
            for (int mt = 0; mt < 4; mt++) {
                uint32_t ah[4], al[4];
                uint32_t aoff = (uint32_t)((wm * 64 + mt * 16 + (tt & 1) * 8 + lr) * 128 +
                                ((ks * 32 + (tt >> 1) * 16) ^ swz));
                ldsm_x4(ah, sb + A_HI + aoff);
                ldsm_x4(al, sb + A_LO + aoff);
#pragma unroll
                for (int nt = 0; nt < 2; nt++) {
#pragma unroll
                    for (int f = 0; f < 2; f++) {
                        float* cc = c[mt][nt * 2 + f];
                        mma16816(cc, ah, &bh[nt][2 * f]);
                        if (MODE == 1) mma16816(cc, ah, &bl[nt][2 * f]);
                        mma16816(cc, al, &bh[nt][2 * f]);
                    }
                }
            }
        }
        __syncthreads();
    }

    // ---- epilogue ----
    if (MODE == 1) {
        float* out = outparam;
#pragma unroll
        for (int mt = 0; mt < 4; mt++) {
            int m = wm * 64 + mt * 16 + (lane >> 2);
#pragma unroll
            for (int nt = 0; nt < 4; nt++) {
                int gn = n0 + wn * 32 + nt * 8 + 2 * (lane & 3);
                if (gn < N) {
                    float b0 = __ldg(bias + gn), b1 = __ldg(bias + gn + 1);
                    float2 v0 = make_float2(c[mt][nt][0] + b0, c[mt][nt][1] + b1);
                    float2 v1 = make_float2(c[mt][nt][2] + b0, c[mt][nt][3] + b1);
                    *(float2*)(out + (size_t)m * N + gn) = v0;
                    *(float2*)(out + (size_t)(m + 8) * N + gn) = v1;
                }
            }
        }
    } else {
        // stage to smem, then write transposed bf16 rows coalesced
        float* sf = (float*)smem;   // [128 m][132]
#pragma unroll
        for (int mt = 0; mt < 4; mt++) {
            int m = wm * 64 + mt * 16 + (lane >> 2);
#pragma unroll
            for (int nt = 0; nt < 4; nt++) {
                int nl = wn * 32 + nt * 8 + 2 * (lane & 3);
                int gn = n0 + nl;
                float b0 = (gn < N) ? __ldg(bias + gn) : 0.f;
                float b1 = (gn + 1 < N) ? __ldg(bias + gn + 1) : 0.f;
                *(float2*)(sf + m * 132 + nl) = make_float2(c[mt][nt][0] + b0, c[mt][nt][1] + b1);
                *(float2*)(sf + (m + 8) * 132 + nl) = make_float2(c[mt][nt][2] + b0, c[mt][nt][3] + b1);
            }
        }
        __syncthreads();
        for (int idx = tid; idx < 128 * 64; idx += 256) {
            int n = idx >> 6, mp = idx & 63;
            int gn = n0 + n;
            if (gn < N) {
                float v0 = sf[(2 * mp) * 132 + n];
                float v1 = sf[(2 * mp + 1) * 132 + n];
                uint32_t packed = pack_hi2(v0, v1);
                *(uint32_t*)((char*)g_vT + ((size_t)gn * R_ + 2 * mp) * 2) = packed;
            }
        }
    }
}

// ============================================================
// Kernel 4: sparse gather-sum (bf16 vT) + scaled add into y
// smem (idx,w) pairs; 2 s per warp via half-warp uint4 row loads.
// ============================================================
#define GTS 64
#define GATHER_SMEM (GTS * KDEG * 8 + R_ * (GTS + 1) * 4)   // 16384 + 33280

__global__ void __launch_bounds__(256)
gather_kernel(const int* __restrict__ sl_idx,
              const float* __restrict__ sl_w,
              float* __restrict__ out) {
    extern __shared__ char gsm[];
    uint2* s_pair = (uint2*)gsm;                       // [GTS*KDEG]
    float* tile = (float*)(gsm + GTS * KDEG * 8);      // [R_][GTS+1]

    int s0 = blockIdx.x * GTS;
    int tid = threadIdx.x;
    int wid = tid >> 5;
    int lane = tid & 31;
    int hh = lane >> 4;        // which s of the warp's pair
    int hl = lane & 15;        // lane within half-warp: 8 m values

    // stage (idx, weight) pairs; out-of-range -> (0, 0.0f): harmless row-0 read * 0
#pragma unroll
    for (int i = 0; i < GTS * KDEG / 256; i++) {
        int e = i * 256 + tid;
        int gs = s0 * KDEG + e;
        uint2 p = make_uint2(0u, 0u);
        if (gs < S_ * KDEG) {
            p.x = (uint32_t)sl_idx[gs];
            p.y = __float_as_uint(sl_w[gs]);
        }
        s_pair[e] = p;
    }
    __syncthreads();

#pragma unroll
    for (int it = 0; it < GTS / 16; it++) {
        int sl = it * 16 + wid * 2 + hh;
        float acc[8];
#pragma unroll
        for (int j = 0; j < 8; j++) acc[j] = 0.f;
#pragma unroll 8
        for (int k = 0; k < KDEG; k++) {
            uint2 p = s_pair[sl * KDEG + k];
            float wk = __uint_as_float(p.y);
            uint4 raw = *(const uint4*)(g_vT + (size_t)p.x * R_ + hl * 8);
            uint32_t rw[4] = {raw.x, raw.y, raw.z, raw.w};
#pragma unroll
            for (int q = 0; q < 4; q++) {
                __nv_bfloat162 bp = *reinterpret_cast<__nv_bfloat162*>(&rw[q]);
                float2 f = __bfloat1622float2(bp);
                acc[2 * q + 0] = fmaf(wk, f.x, acc[2 * q + 0]);
                acc[2 * q + 1] = fmaf(wk, f.y, acc[2 * q + 1]);
            }
        }
#pragma unroll
        for (int j = 0; j < 8; j++)
            tile[(hl * 8 + j) * (GTS + 1) + sl] = acc[j];
    }
    __syncthreads();

    int nvalid = S_ - s0;
    if (nvalid > GTS) nvalid = GTS;
    for (int it = tid; it < R_ * GTS; it += 256) {
        int sl = it & (GTS - 1);
        int row = it >> 6;
        if (sl < nvalid) {
            size_t o = (size_t)row * S_ + s0 + sl;
            out[o] += SLM_SCALE * tile[row * (GTS + 1) + sl];
        }
    }
}

// ============================================================
extern "C" void kernel_launch(void* const* d_in, const int* in_sizes, int n_in,
                              void* d_out, int out_size) {
    const float* x     = (const float*)d_in[0];
    const float* gamma = (const float*)d_in[1];
    const float* beta  = (const float*)d_in[2];
    const float* W1    = (const float*)d_in[3];
    const float* b1    = (const float*)d_in[4];
    const float* W2    = (const float*)d_in[5];
    const float* b2    = (const float*)d_in[6];
    const float* Wslm  = (const float*)d_in[7];
    const float* bslm  = (const float*)d_in[8];
    const float* slw   = (const float*)d_in[9];
    const int*   slidx = (const int*)d_in[10];
    float* out = (float*)d_out;

    cudaFuncSetAttribute(mma_gemm<1>, cudaFuncAttributeMaxDynamicSharedMemorySize, GEMM_SMEM);
    cudaFuncSetAttribute(mma_gemm<2>, cudaFuncAttributeMaxDynamicSharedMemorySize, GEMM_SMEM);
    cudaFuncSetAttribute(gather_kernel, cudaFuncAttributeMaxDynamicSharedMemorySize, GATHER_SMEM);

    bn_stats_kernel<<<L_, 256>>>(x, gamma, beta);
    h_kernel<<<H_ / 64, 256>>>(x, W1, b1);
    mma_gemm<1><<<(S_ + 127) / 128, 256, GEMM_SMEM>>>(W2, b2, out, S_);
    mma_gemm<2><<<(V_ + 127) / 128, 256, GEMM_SMEM>>>(Wslm, bslm, nullptr, V_);
    gather_kernel<<<(S_ + 63) / 64, 256, GATHER_SMEM>>>(slidx, slw, out);
}

// round 12
// speedup vs baseline: 1.4700x; 1.0974x over previous
#include <cuda_runtime.h>
#include <cuda_bf16.h>
#include <cstdint>

#define B_ 2
#define L_ 64
#define D_ 1024
#define H_ 512
#define S_ 50000
#define V_ 40000
#define KDEG 32
#define R_ 128
#define BN_EPS 1e-5f
#define SLM_SCALE 0.1f

// ---- scratch (device globals; no allocation allowed) ----
__device__ float g_scale[L_];
__device__ float g_shift[L_];
__device__ __nv_bfloat16 g_h_hi[R_ * H_];
__device__ __nv_bfloat16 g_h_lo[R_ * H_];
__device__ __nv_bfloat16 g_vT[(size_t)V_ * R_];   // transposed v (bf16): [V][128]

// ============================================================
// helpers
// ============================================================
__device__ __forceinline__ uint32_t smem_u32(const void* p) {
    uint32_t a;
    asm("{ .reg .u64 t; cvta.to.shared.u64 t, %1; cvt.u32.u64 %0, t; }" : "=r"(a) : "l"(p));
    return a;
}
__device__ __forceinline__ void ldsm_x4(uint32_t* r, uint32_t addr) {
    asm volatile("ldmatrix.sync.aligned.m8n8.x4.shared.b16 {%0,%1,%2,%3}, [%4];"
        : "=r"(r[0]), "=r"(r[1]), "=r"(r[2]), "=r"(r[3]) : "r"(addr));
}
__device__ __forceinline__ void ldsm_x4_t(uint32_t* r, uint32_t addr) {
    asm volatile("ldmatrix.sync.aligned.m8n8.x4.trans.shared.b16 {%0,%1,%2,%3}, [%4];"
        : "=r"(r[0]), "=r"(r[1]), "=r"(r[2]), "=r"(r[3]) : "r"(addr));
}
__device__ __forceinline__ void mma16816(float* c, const uint32_t* a, const uint32_t* b) {
    asm volatile("mma.sync.aligned.m16n8k16.row.col.f32.bf16.bf16.f32 "
        "{%0,%1,%2,%3}, {%4,%5,%6,%7}, {%8,%9}, {%0,%1,%2,%3};"
        : "+f"(c[0]), "+f"(c[1]), "+f"(c[2]), "+f"(c[3])
        : "r"(a[0]), "r"(a[1]), "r"(a[2]), "r"(a[3]), "r"(b[0]), "r"(b[1]));
}
__device__ __forceinline__ uint32_t pack_hi2(float x, float y) {
    __nv_bfloat16 hx = __float2bfloat16(x), hy = __float2bfloat16(y);
    return (uint32_t)__bfloat16_as_ushort(hx) | ((uint32_t)__bfloat16_as_ushort(hy) << 16);
}
__device__ __forceinline__ uint32_t pack_lo2(float x, float y) {
    __nv_bfloat16 hx = __float2bfloat16(x), hy = __float2bfloat16(y);
    __nv_bfloat16 lx = __float2bfloat16(x - __bfloat162float(hx));
    __nv_bfloat16 ly = __float2bfloat16(y - __bfloat162float(hy));
    return (uint32_t)__bfloat16_as_ushort(lx) | ((uint32_t)__bfloat16_as_ushort(ly) << 16);
}

// ============================================================
// Kernel 1: BatchNorm stats
// ============================================================
__global__ void bn_stats_kernel(const float* __restrict__ x,
                                const float* __restrict__ gamma,
                                const float* __restrict__ beta) {
    int l = blockIdx.x;
    int t = threadIdx.x;
    float s = 0.f, sq = 0.f;
    for (int b = 0; b < B_; b++) {
        const float* row = x + ((size_t)(b * L_ + l)) * D_;
        for (int d = t; d < D_; d += 256) {
            float v = row[d];
            s += v; sq += v * v;
        }
    }
    __shared__ float sh_s[256], sh_q[256];
    sh_s[t] = s; sh_q[t] = sq;
    __syncthreads();
    for (int off = 128; off > 0; off >>= 1) {
        if (t < off) { sh_s[t] += sh_s[t + off]; sh_q[t] += sh_q[t + off]; }
        __syncthreads();
    }
    if (t == 0) {
        float inv = 1.f / (float)(B_ * D_);
        float mean = sh_s[0] * inv;
        float var = sh_q[0] * inv - mean * mean;
        float sc = gamma[l] * rsqrtf(var + BN_EPS);
        g_scale[l] = sc;
        g_shift[l] = beta[l] - mean * sc;
    }
}

// ============================================================
// Kernel 2: h = relu(BN(x)@W1+b1), emitted as split bf16 (hi/lo)
// ============================================================
__global__ void h_kernel(const float* __restrict__ A,
                         const float* __restrict__ W,
                         const float* __restrict__ bias) {
    constexpr int K = D_, N = H_;
    constexpr int BK = 16, TM = 8, TN = 4;
    __shared__ float As[BK][128];
    __shared__ float Bs[BK][64];

    const int tid = threadIdx.x;
    const int n0 = blockIdx.x * 64;
    const int trow = tid & 15;
    const int tcol = tid >> 4;
    const int kq = tid & 3;
    const int mA = tid >> 2;
    const int nq = tid & 15;
    const int kB = tid >> 4;

    float acc[TM][TN];
#pragma unroll
    for (int i = 0; i < TM; i++)
#pragma unroll
        for (int j = 0; j < TN; j++) acc[i][j] = 0.f;

    for (int k0 = 0; k0 < K; k0 += BK) {
#pragma unroll
        for (int mm = 0; mm < 2; mm++) {
            int m = mA + mm * 64;
            float4 a = *(const float4*)(A + (size_t)m * K + k0 + kq * 4);
            float sc = g_scale[m & (L_ - 1)];
            float sh = g_shift[m & (L_ - 1)];
            a.x = fmaf(a.x, sc, sh); a.y = fmaf(a.y, sc, sh);
            a.z = fmaf(a.z, sc, sh); a.w = fmaf(a.w, sc, sh);
            As[kq * 4 + 0][m] = a.x; As[kq * 4 + 1][m] = a.y;
            As[kq * 4 + 2][m] = a.z; As[kq * 4 + 3][m] = a.w;
        }
        {
            int n = n0 + nq * 4;
            float4 b = *(const float4*)(W + (size_t)(k0 + kB) * N + n);
            *(float4*)&Bs[kB][nq * 4] = b;
        }
        __syncthreads();
#pragma unroll
        for (int k = 0; k < BK; k++) {
            float a[TM], bb[TN];
#pragma unroll
            for (int i = 0; i < TM; i++) a[i] = As[k][trow * TM + i];
#pragma unroll
            for (int j = 0; j < TN; j++) bb[j] = Bs[k][tcol * TN + j];
#pragma unroll
            for (int i = 0; i < TM; i++)
#pragma unroll
                for (int j = 0; j < TN; j++) acc[i][j] = fmaf(a[i], bb[j], acc[i][j]);
        }
        __syncthreads();
    }

#pragma unroll
    for (int j = 0; j < TN; j++) {
        int n = n0 + tcol * TN + j;
        float bz = bias[n];
#pragma unroll
        for (int i = 0; i < TM; i++) {
            int m = trow * TM + i;
            float val = fmaxf(acc[i][j] + bz, 0.f);
            __nv_bfloat16 hi = __float2bfloat16(val);
            g_h_hi[(size_t)m * H_ + n] = hi;
            g_h_lo[(size_t)m * H_ + n] = __float2bfloat16(val - __bfloat162float(hi));
        }
    }
}

// ============================================================
// Kernel 3: split-bf16 mma.sync GEMM  C[128,N] = h[128,512]@W[512,N] + bias
// MODE 1: 3-pass, epilogue = y + FUSED sparse gather -> out fp32 (single store)
// MODE 2: 2-pass (B_LO dropped), out = g_vT bf16 [N][128]
// CTA: 256 threads (8 warps, 2M x 4N), tile 128x128, K chunks of 64.
// SF_PITCH must be EVEN (float2 epilogue stores) and 8*P mod 32 != 0
// (gather RMW bank conflicts): 134 -> 2-way conflicts, aligned.
// ============================================================
#define A_HI 0
#define A_LO 16384
#define B_HI 32768
#define B_LO 49152
#define SF_PITCH 134
#define PAIR_OFF (128 * SF_PITCH * 4)           // 68608
#define GEMM_SMEM_1 (PAIR_OFF + 128 * KDEG * 8) // 68608 + 32768 = 101376
#define GEMM_SMEM_2 (128 * SF_PITCH * 4)        // 68608 (>= stage 64KB)

template <int MODE>
__global__ void __launch_bounds__(256, 2)
mma_gemm(const float* __restrict__ W, const float* __restrict__ bias,
         float* __restrict__ outparam, int N,
         const int* __restrict__ sl_idx, const float* __restrict__ sl_w) {
    extern __shared__ char smem[];
    const uint32_t sb = smem_u32(smem);
    const int tid = threadIdx.x;
    const int lane = tid & 31;
    const int wid = tid >> 5;
    const int wm = wid >> 2;         // 0..1
    const int wn = wid & 3;          // 0..3
    const int n0 = blockIdx.x * 128;

    const int tt = lane >> 3;        // ldmatrix tile group 0..3
    const int lr = lane & 7;
    const uint32_t swz = (uint32_t)lr << 4;

    // MODE 1: stage (idx,w) pairs for this tile's 128 s up front (hidden behind GEMM)
    if (MODE == 1) {
        uint2* s_pair = (uint2*)(smem + PAIR_OFF);
#pragma unroll
        for (int g = 0; g < 4; g++) {
            int e4 = (g * 256 + tid) * 4;          // element group of 4
            int gs = n0 * KDEG + e4;
            int4 i4 = make_int4(0, 0, 0, 0);
            float4 w4 = make_float4(0.f, 0.f, 0.f, 0.f);
            if (gs + 3 < S_ * KDEG) {              // S_*KDEG divisible by 4
                i4 = *(const int4*)(sl_idx + gs);
                w4 = *(const float4*)(sl_w + gs);
            }
            s_pair[e4 + 0] = make_uint2((uint32_t)i4.x, __float_as_uint(w4.x));
            s_pair[e4 + 1] = make_uint2((uint32_t)i4.y, __float_as_uint(w4.y));
            s_pair[e4 + 2] = make_uint2((uint32_t)i4.z, __float_as_uint(w4.z));
            s_pair[e4 + 3] = make_uint2((uint32_t)i4.w, __float_as_uint(w4.w));
        }
    }

    float c[4][4][4];
#pragma unroll
    for (int a = 0; a < 4; a++)
#pragma unroll
        for (int b = 0; b < 4; b++)
#pragma unroll
            for (int d = 0; d < 4; d++) c[a][b][d] = 0.f;

    for (int ch = 0; ch < 8; ch++) {
        const int k0 = ch * 64;

        // ---- fill A: [128 m][64 k] bf16 hi/lo, swizzled 128B rows
#pragma unroll
        for (int i = 0; i < 4; i++) {
            int idx = i * 256 + tid;
            int m = idx >> 3, q = idx & 7;
            uint32_t off = (uint32_t)(m * 128 + ((q * 16) ^ ((m & 7) << 4)));
            *(uint4*)(smem + A_HI + off) = *(const uint4*)(g_h_hi + (size_t)m * H_ + k0 + q * 8);
            *(uint4*)(smem + A_LO + off) = *(const uint4*)(g_h_lo + (size_t)m * H_ + k0 + q * 8);
        }
        // ---- fill B: [64 k][128 n] bf16 hi (+lo in MODE 1), rows 256B
#pragma unroll
        for (int i = 0; i < 8; i++) {
            int k = (tid >> 5) + i * 8;
            int nl = (tid & 31) * 4;
            int gn = n0 + nl;
            float4 w4 = make_float4(0.f, 0.f, 0.f, 0.f);
            if (gn < N) w4 = *(const float4*)(W + (size_t)(k0 + k) * N + gn);
            uint32_t off = (uint32_t)(k * 256 + ((nl * 2) ^ ((k & 7) << 4)));
            uint2 hv;
            hv.x = pack_hi2(w4.x, w4.y); hv.y = pack_hi2(w4.z, w4.w);
            *(uint2*)(smem + B_HI + off) = hv;
            if (MODE == 1) {
                uint2 lv;
                lv.x = pack_lo2(w4.x, w4.y); lv.y = pack_lo2(w4.z, w4.w);
                *(uint2*)(smem + B_LO + off) = lv;
            }
        }
        __syncthreads();

        // ---- consume: 4 k-steps of 16
#pragma unroll
        for (int ks = 0; ks < 4; ks++) {
            uint32_t bh[2][4], bl[2][4];
#pragma unroll
            for (int nt = 0; nt < 2; nt++) {
                uint32_t boff = (uint32_t)((ks * 16 + (tt & 1) * 8 + lr) * 256 +
                                ((wn * 64 + nt * 32 + (tt >> 1) * 16) ^ swz));
                ldsm_x4_t(bh[nt], sb + B_HI + boff);
                if (MODE == 1) ldsm_x4_t(bl[nt], sb + B_LO + boff);
            }
#pragma unroll
            for (int mt = 0; mt < 4; mt++) {
                uint32_t ah[4], al[4];
                uint32_t aoff = (uint32_t)((wm * 64 + mt * 16 + (tt & 1) * 8 + lr) * 128 +
                                ((ks * 32 + (tt >> 1) * 16) ^ swz));
                ldsm_x4(ah, sb + A_HI + aoff);
                ldsm_x4(al, sb + A_LO + aoff);
#pragma unroll
                for (int nt = 0; nt < 2; nt++) {
#pragma unroll
                    for (int f = 0; f < 2; f++) {
                        float* cc = c[mt][nt * 2 + f];
                        mma16816(cc, ah, &bh[nt][2 * f]);
                        if (MODE == 1) mma16816(cc, ah, &bl[nt][2 * f]);
                        mma16816(cc, al, &bh[nt][2 * f]);
                    }
                }
            }
        }
        __syncthreads();
    }

    // ---- epilogue: stage fp32 tile [128 m][SF_PITCH] with bias ----
    float* sf = (float*)smem;
#pragma unroll
    for (int mt = 0; mt < 4; mt++) {
        int m = wm * 64 + mt * 16 + (lane >> 2);
#pragma unroll
        for (int nt = 0; nt < 4; nt++) {
            int nl = wn * 32 + nt * 8 + 2 * (lane & 3);
            int gn = n0 + nl;
            float b0 = (gn < N) ? __ldg(bias + gn) : 0.f;
            float b1 = (gn + 1 < N) ? __ldg(bias + gn + 1) : 0.f;
            *(float2*)(sf + m * SF_PITCH + nl) = make_float2(c[mt][nt][0] + b0, c[mt][nt][1] + b1);
            *(float2*)(sf + (m + 8) * SF_PITCH + nl) = make_float2(c[mt][nt][2] + b0, c[mt][nt][3] + b1);
        }
    }
    __syncthreads();

    if (MODE == 1) {
        // fused gather: 2 s per warp per iter via half-warp uint4 row loads
        const uint2* s_pair = (const uint2*)(smem + PAIR_OFF);
        const int hh = lane >> 4;      // which s of the warp pair
        const int hl = lane & 15;      // 8 m-values per lane
#pragma unroll
        for (int it = 0; it < 8; it++) {
            int sl = it * 16 + wid * 2 + hh;
            float acc[8];
#pragma unroll
            for (int j = 0; j < 8; j++) acc[j] = 0.f;
#pragma unroll 8
            for (int k = 0; k < KDEG; k++) {
                uint2 p = s_pair[sl * KDEG + k];
                float wk = __uint_as_float(p.y);
                uint4 raw = *(const uint4*)(g_vT + (size_t)p.x * R_ + hl * 8);
                uint32_t rw[4] = {raw.x, raw.y, raw.z, raw.w};
#pragma unroll
                for (int q = 0; q < 4; q++) {
                    __nv_bfloat162 bp = *reinterpret_cast<__nv_bfloat162*>(&rw[q]);
                    float2 f = __bfloat1622float2(bp);
                    acc[2 * q + 0] = fmaf(wk, f.x, acc[2 * q + 0]);
                    acc[2 * q + 1] = fmaf(wk, f.y, acc[2 * q + 1]);
                }
            }
#pragma unroll
            for (int j = 0; j < 8; j++)
                sf[(hl * 8 + j) * SF_PITCH + sl] += SLM_SCALE * acc[j];
        }
        __syncthreads();
        // single coalesced store of y + 0.1*slm
        float* out = outparam;
        for (int idx = tid; idx < 128 * 128; idx += 256) {
            int m = idx >> 7, n = idx & 127;
            int gn = n0 + n;
            if (gn < N) out[(size_t)m * N + gn] = sf[m * SF_PITCH + n];
        }
    } else {
        // write transposed bf16 rows coalesced: vT[n][m]
        for (int idx = tid; idx < 128 * 64; idx += 256) {
            int n = idx >> 6, mp = idx & 63;
            int gn = n0 + n;
            if (gn < N) {
                float v0 = sf[(2 * mp) * SF_PITCH + n];
                float v1 = sf[(2 * mp + 1) * SF_PITCH + n];
                uint32_t packed = pack_hi2(v0, v1);
                *(uint32_t*)((char*)g_vT + ((size_t)gn * R_ + 2 * mp) * 2) = packed;
            }
        }
    }
}

// ============================================================
extern "C" void kernel_launch(void* const* d_in, const int* in_sizes, int n_in,
                              void* d_out, int out_size) {
    const float* x     = (const float*)d_in[0];
    const float* gamma = (const float*)d_in[1];
    const float* beta  = (const float*)d_in[2];
    const float* W1    = (const float*)d_in[3];
    const float* b1    = (const float*)d_in[4];
    const float* W2    = (const float*)d_in[5];
    const float* b2    = (const float*)d_in[6];
    const float* Wslm  = (const float*)d_in[7];
    const float* bslm  = (const float*)d_in[8];
    const float* slw   = (const float*)d_in[9];
    const int*   slidx = (const int*)d_in[10];
    float* out = (float*)d_out;

    cudaFuncSetAttribute(mma_gemm<1>, cudaFuncAttributeMaxDynamicSharedMemorySize, GEMM_SMEM_1);
    cudaFuncSetAttribute(mma_gemm<2>, cudaFuncAttributeMaxDynamicSharedMemorySize, GEMM_SMEM_2);

    bn_stats_kernel<<<L_, 256>>>(x, gamma, beta);
    h_kernel<<<H_ / 64, 256>>>(x, W1, b1);
    // vT first (gather input), then y with fused gather
    mma_gemm<2><<<(V_ + 127) / 128, 256, GEMM_SMEM_2>>>(Wslm, bslm, nullptr, V_, nullptr, nullptr);
    mma_gemm<1><<<(S_ + 127) / 128, 256, GEMM_SMEM_1>>>(W2, b2, out, S_, slidx, slw);
}

// round 13
// speedup vs baseline: 2.0158x; 1.3713x over previous
#include <cuda_runtime.h>
#include <cuda_fp16.h>
#include <cstdint>

#define B_ 2
#define L_ 64
#define D_ 1024
#define H_ 512
#define S_ 50000
#define V_ 40000
#define KDEG 32
#define R_ 128
#define BN_EPS 1e-5f
#define SLM_SCALE 0.1f

// ---- scratch (device globals; no allocation allowed) ----
__device__ float g_scale[L_];
__device__ float g_shift[L_];
__device__ __half g_h_hi[R_ * H_];
__device__ __half g_h_lo[R_ * H_];
__device__ __half g_vT[(size_t)V_ * R_];   // transposed v (fp16): [V][128]

// ============================================================
// helpers
// ============================================================
__device__ __forceinline__ uint32_t smem_u32(const void* p) {
    uint32_t a;
    asm("{ .reg .u64 t; cvta.to.shared.u64 t, %1; cvt.u32.u64 %0, t; }" : "=r"(a) : "l"(p));
    return a;
}
__device__ __forceinline__ void ldsm_x4(uint32_t* r, uint32_t addr) {
    asm volatile("ldmatrix.sync.aligned.m8n8.x4.shared.b16 {%0,%1,%2,%3}, [%4];"
        : "=r"(r[0]), "=r"(r[1]), "=r"(r[2]), "=r"(r[3]) : "r"(addr));
}
__device__ __forceinline__ void ldsm_x4_t(uint32_t* r, uint32_t addr) {
    asm volatile("ldmatrix.sync.aligned.m8n8.x4.trans.shared.b16 {%0,%1,%2,%3}, [%4];"
        : "=r"(r[0]), "=r"(r[1]), "=r"(r[2]), "=r"(r[3]) : "r"(addr));
}
__device__ __forceinline__ void mma16816(float* c, const uint32_t* a, const uint32_t* b) {
    asm volatile("mma.sync.aligned.m16n8k16.row.col.f32.f16.f16.f32 "
        "{%0,%1,%2,%3}, {%4,%5,%6,%7}, {%8,%9}, {%0,%1,%2,%3};"
        : "+f"(c[0]), "+f"(c[1]), "+f"(c[2]), "+f"(c[3])
        : "r"(a[0]), "r"(a[1]), "r"(a[2]), "r"(a[3]), "r"(b[0]), "r"(b[1]));
}
__device__ __forceinline__ uint32_t pack_h2(float x, float y) {
    __half2 h = __floats2half2_rn(x, y);
    return *reinterpret_cast<uint32_t*>(&h);
}
__device__ __forceinline__ uint32_t pack_l2(float x, float y) {
    __half hx = __float2half_rn(x), hy = __float2half_rn(y);
    return pack_h2(x - __half2float(hx), y - __half2float(hy));
}

// ============================================================
// Kernel 1: BatchNorm stats
// ============================================================
__global__ void bn_stats_kernel(const float* __restrict__ x,
                                const float* __restrict__ gamma,
                                const float* __restrict__ beta) {
    int l = blockIdx.x;
    int t = threadIdx.x;
    float s = 0.f, sq = 0.f;
    for (int b = 0; b < B_; b++) {
        const float* row = x + ((size_t)(b * L_ + l)) * D_;
        for (int d = t; d < D_; d += 256) {
            float v = row[d];
            s += v; sq += v * v;
        }
    }
    __shared__ float sh_s[256], sh_q[256];
    sh_s[t] = s; sh_q[t] = sq;
    __syncthreads();
    for (int off = 128; off > 0; off >>= 1) {
        if (t < off) { sh_s[t] += sh_s[t + off]; sh_q[t] += sh_q[t + off]; }
        __syncthreads();
    }
    if (t == 0) {
        float inv = 1.f / (float)(B_ * D_);
        float mean = sh_s[0] * inv;
        float var = sh_q[0] * inv - mean * mean;
        float sc = gamma[l] * rsqrtf(var + BN_EPS);
        g_scale[l] = sc;
        g_shift[l] = beta[l] - mean * sc;
    }
}

// ============================================================
// Kernel 2: unified fp16 mma.sync GEMM   C[128,N] = A[128,K]@W[K,N] + bias
// MODE 0: A = BN(x) (fp32->split fp16 in fill), 3-pass, K=1024,
//         epilogue = relu + split -> g_h_hi/lo            (h)
// MODE 1: A = g_h hi/lo, B single fp16, 2-pass, K=512,
//         epilogue = y + FUSED sparse gather -> out fp32  (y+slm)
// MODE 2: A = g_h hi only, 1-pass, K=512,
//         epilogue = vT fp16 transposed [N][128]          (v)
// CTA: 256 threads (8 warps, 2M x 4N), tile 128x128, K chunks of 64.
// ============================================================
#define A_HI 0
#define A_LO 16384
#define B_HI 32768
#define B_LO 49152
#define SF_PITCH 134
#define PAIR_OFF (128 * SF_PITCH * 4)           // 68608
#define GEMM_SMEM_0 (128 * SF_PITCH * 4)        // 68608
#define GEMM_SMEM_1 (PAIR_OFF + 128 * KDEG * 8) // 101376
#define GEMM_SMEM_2 (128 * SF_PITCH * 4)        // 68608

template <int MODE>
__global__ void __launch_bounds__(256, 2)
mma_gemm(const float* __restrict__ W, const float* __restrict__ bias,
         float* __restrict__ outparam, int N,
         const float* __restrict__ X,
         const int* __restrict__ sl_idx, const float* __restrict__ sl_w) {
    extern __shared__ char smem[];
    const uint32_t sb = smem_u32(smem);
    const int tid = threadIdx.x;
    const int lane = tid & 31;
    const int wid = tid >> 5;
    const int wm = wid >> 2;         // 0..1
    const int wn = wid & 3;          // 0..3
    const int n0 = blockIdx.x * 128;

    const int tt = lane >> 3;        // ldmatrix tile group 0..3
    const int lr = lane & 7;
    const uint32_t swz = (uint32_t)lr << 4;

    // MODE 1: stage (idx,w) pairs for this tile's 128 s up front
    if (MODE == 1) {
        uint2* s_pair = (uint2*)(smem + PAIR_OFF);
#pragma unroll
        for (int g = 0; g < 4; g++) {
            int e4 = (g * 256 + tid) * 4;
            int gs = n0 * KDEG + e4;
            int4 i4 = make_int4(0, 0, 0, 0);
            float4 w4 = make_float4(0.f, 0.f, 0.f, 0.f);
            if (gs + 3 < S_ * KDEG) {
                i4 = *(const int4*)(sl_idx + gs);
                w4 = *(const float4*)(sl_w + gs);
            }
            s_pair[e4 + 0] = make_uint2((uint32_t)i4.x, __float_as_uint(w4.x));
            s_pair[e4 + 1] = make_uint2((uint32_t)i4.y, __float_as_uint(w4.y));
            s_pair[e4 + 2] = make_uint2((uint32_t)i4.z, __float_as_uint(w4.z));
            s_pair[e4 + 3] = make_uint2((uint32_t)i4.w, __float_as_uint(w4.w));
        }
    }

    float c[4][4][4];
#pragma unroll
    for (int a = 0; a < 4; a++)
#pragma unroll
        for (int b = 0; b < 4; b++)
#pragma unroll
            for (int d = 0; d < 4; d++) c[a][b][d] = 0.f;

    const int NCH = (MODE == 0) ? 16 : 8;
    for (int ch = 0; ch < NCH; ch++) {
        const int k0 = ch * 64;

        // ---- fill A: [128 m][64 k] fp16, swizzled 128B rows
#pragma unroll
        for (int i = 0; i < 4; i++) {
            int idx = i * 256 + tid;
            int m = idx >> 3, q = idx & 7;
            uint32_t off = (uint32_t)(m * 128 + ((q * 16) ^ ((m & 7) << 4)));
            if (MODE == 0) {
                const float* xs = X + (size_t)m * D_ + k0 + q * 8;
                float4 a0 = *(const float4*)xs;
                float4 a1 = *(const float4*)(xs + 4);
                float sc = g_scale[m & (L_ - 1)];
                float sh = g_shift[m & (L_ - 1)];
                a0.x = fmaf(a0.x, sc, sh); a0.y = fmaf(a0.y, sc, sh);
                a0.z = fmaf(a0.z, sc, sh); a0.w = fmaf(a0.w, sc, sh);
                a1.x = fmaf(a1.x, sc, sh); a1.y = fmaf(a1.y, sc, sh);
                a1.z = fmaf(a1.z, sc, sh); a1.w = fmaf(a1.w, sc, sh);
                uint4 vh, vl;
                vh.x = pack_h2(a0.x, a0.y); vh.y = pack_h2(a0.z, a0.w);
                vh.z = pack_h2(a1.x, a1.y); vh.w = pack_h2(a1.z, a1.w);
                vl.x = pack_l2(a0.x, a0.y); vl.y = pack_l2(a0.z, a0.w);
                vl.z = pack_l2(a1.x, a1.y); vl.w = pack_l2(a1.z, a1.w);
                *(uint4*)(smem + A_HI + off) = vh;
                *(uint4*)(smem + A_LO + off) = vl;
            } else {
                *(uint4*)(smem + A_HI + off) = *(const uint4*)(g_h_hi + (size_t)m * H_ + k0 + q * 8);
                if (MODE == 1)
                    *(uint4*)(smem + A_LO + off) = *(const uint4*)(g_h_lo + (size_t)m * H_ + k0 + q * 8);
            }
        }
        // ---- fill B: [64 k][128 n] fp16 hi (+lo in MODE 0), rows 256B
#pragma unroll
        for (int i = 0; i < 8; i++) {
            int k = (tid >> 5) + i * 8;
            int nl = (tid & 31) * 4;
            int gn = n0 + nl;
            float4 w4 = make_float4(0.f, 0.f, 0.f, 0.f);
            if (gn < N) w4 = *(const float4*)(W + (size_t)(k0 + k) * N + gn);
            uint32_t off = (uint32_t)(k * 256 + ((nl * 2) ^ ((k & 7) << 4)));
            uint2 hv;
            hv.x = pack_h2(w4.x, w4.y); hv.y = pack_h2(w4.z, w4.w);
            *(uint2*)(smem + B_HI + off) = hv;
            if (MODE == 0) {
                uint2 lv;
                lv.x = pack_l2(w4.x, w4.y); lv.y = pack_l2(w4.z, w4.w);
                *(uint2*)(smem + B_LO + off) = lv;
            }
        }
        __syncthreads();

        // ---- consume: 4 k-steps of 16
#pragma unroll
        for (int ks = 0; ks < 4; ks++) {
            uint32_t bh[2][4], bl[2][4];
#pragma unroll
            for (int nt = 0; nt < 2; nt++) {
                uint32_t boff = (uint32_t)((ks * 16 + (tt & 1) * 8 + lr) * 256 +
                                ((wn * 64 + nt * 32 + (tt >> 1) * 16) ^ swz));
                ldsm_x4_t(bh[nt], sb + B_HI + boff);
                if (MODE == 0) ldsm_x4_t(bl[nt], sb + B_LO + boff);
            }
#pragma unroll
            for (int mt = 0; mt < 4; mt++) {
                uint32_t ah[4], al[4];
                uint32_t aoff = (uint32_t)((wm * 64 + mt * 16 + (tt & 1) * 8 + lr) * 128 +
                                ((ks * 32 + (tt >> 1) * 16) ^ swz));
                ldsm_x4(ah, sb + A_HI + aoff);
                if (MODE != 2) ldsm_x4(al, sb + A_LO + aoff);
#pragma unroll
                for (int nt = 0; nt < 2; nt++) {
#pragma unroll
                    for (int f = 0; f < 2; f++) {
                        float* cc = c[mt][nt * 2 + f];
                        mma16816(cc, ah, &bh[nt][2 * f]);
                        if (MODE == 0) mma16816(cc, ah, &bl[nt][2 * f]);
                        if (MODE != 2) mma16816(cc, al, &bh[nt][2 * f]);
                    }
                }
            }
        }
        __syncthreads();
    }

    // ---- epilogue: stage fp32 tile [128 m][SF_PITCH] with bias ----
    float* sf = (float*)smem;
#pragma unroll
    for (int mt = 0; mt < 4; mt++) {
        int m = wm * 64 + mt * 16 + (lane >> 2);
#pragma unroll
        for (int nt = 0; nt < 4; nt++) {
            int nl = wn * 32 + nt * 8 + 2 * (lane & 3);
            int gn = n0 + nl;
            float b0 = (gn < N) ? __ldg(bias + gn) : 0.f;
            float b1 = (gn + 1 < N) ? __ldg(bias + gn + 1) : 0.f;
            *(float2*)(sf + m * SF_PITCH + nl) = make_float2(c[mt][nt][0] + b0, c[mt][nt][1] + b1);
            *(float2*)(sf + (m + 8) * SF_PITCH + nl) = make_float2(c[mt][nt][2] + b0, c[mt][nt][3] + b1);
        }
    }
    __syncthreads();

    if (MODE == 0) {
        // relu + fp16 split -> g_h_hi/lo row-major [m][H_]
        for (int idx = tid; idx < 128 * 64; idx += 256) {
            int m = idx >> 6, np = idx & 63;
            float v0 = fmaxf(sf[m * SF_PITCH + 2 * np], 0.f);
            float v1 = fmaxf(sf[m * SF_PITCH + 2 * np + 1], 0.f);
            uint32_t hp = pack_h2(v0, v1);
            uint32_t lp = pack_l2(v0, v1);
            *(uint32_t*)((char*)g_h_hi + ((size_t)m * H_ + n0 + 2 * np) * 2) = hp;
            *(uint32_t*)((char*)g_h_lo + ((size_t)m * H_ + n0 + 2 * np) * 2) = lp;
        }
    } else if (MODE == 1) {
        // fused gather: 2 s per warp per iter via half-warp uint4 row loads
        const uint2* s_pair = (const uint2*)(smem + PAIR_OFF);
        const int hh = lane >> 4;
        const int hl = lane & 15;
#pragma unroll
        for (int it = 0; it < 8; it++) {
            int sl = it * 16 + wid * 2 + hh;
            float acc[8];
#pragma unroll
            for (int j = 0; j < 8; j++) acc[j] = 0.f;
#pragma unroll 8
            for (int k = 0; k < KDEG; k++) {
                uint2 p = s_pair[sl * KDEG + k];
                float wk = __uint_as_float(p.y);
                uint4 raw = *(const uint4*)(g_vT + (size_t)p.x * R_ + hl * 8);
                uint32_t rw[4] = {raw.x, raw.y, raw.z, raw.w};
#pragma unroll
                for (int q = 0; q < 4; q++) {
                    __half2 hp = *reinterpret_cast<__half2*>(&rw[q]);
                    float2 f = __half22float2(hp);
                    acc[2 * q + 0] = fmaf(wk, f.x, acc[2 * q + 0]);
                    acc[2 * q + 1] = fmaf(wk, f.y, acc[2 * q + 1]);
                }
            }
#pragma unroll
            for (int j = 0; j < 8; j++)
                sf[(hl * 8 + j) * SF_PITCH + sl] += SLM_SCALE * acc[j];
        }
        __syncthreads();
        float* out = outparam;
        for (int idx = tid; idx < 128 * 128; idx += 256) {
            int m = idx >> 7, n = idx & 127;
            int gn = n0 + n;
            if (gn < N) out[(size_t)m * N + gn] = sf[m * SF_PITCH + n];
        }
    } else {
        // write transposed fp16 rows coalesced: vT[n][m]
        for (int idx = tid; idx < 128 * 64; idx += 256) {
            int n = idx >> 6, mp = idx & 63;
            int gn = n0 + n;
            if (gn < N) {
                float v0 = sf[(2 * mp) * SF_PITCH + n];
                float v1 = sf[(2 * mp + 1) * SF_PITCH + n];
                uint32_t packed = pack_h2(v0, v1);
                *(uint32_t*)((char*)g_vT + ((size_t)gn * R_ + 2 * mp) * 2) = packed;
            }
        }
    }
}

// ============================================================
extern "C" void kernel_launch(void* const* d_in, const int* in_sizes, int n_in,
                              void* d_out, int out_size) {
    const float* x     = (const float*)d_in[0];
    const float* gamma = (const float*)d_in[1];
    const float* beta  = (const float*)d_in[2];
    const float* W1    = (const float*)d_in[3];
    const float* b1    = (const float*)d_in[4];
    const float* W2    = (const float*)d_in[5];
    const float* b2    = (const float*)d_in[6];
    const float* Wslm  = (const float*)d_in[7];
    const float* bslm  = (const float*)d_in[8];
    const float* slw   = (const float*)d_in[9];
    const int*   slidx = (const int*)d_in[10];
    float* out = (float*)d_out;

    cudaFuncSetAttribute(mma_gemm<0>, cudaFuncAttributeMaxDynamicSharedMemorySize, GEMM_SMEM_0);
    cudaFuncSetAttribute(mma_gemm<1>, cudaFuncAttributeMaxDynamicSharedMemorySize, GEMM_SMEM_1);
    cudaFuncSetAttribute(mma_gemm<2>, cudaFuncAttributeMaxDynamicSharedMemorySize, GEMM_SMEM_2);

    bn_stats_kernel<<<L_, 256>>>(x, gamma, beta);
    // h = relu(BN(x)@W1+b1) on tensor cores (split fp16, 3-pass)
    mma_gemm<0><<<H_ / 128, 256, GEMM_SMEM_0>>>(W1, b1, nullptr, H_, x, nullptr, nullptr);
    // vT first (gather input, 1-pass), then y with fused gather (2-pass)
    mma_gemm<2><<<(V_ + 127) / 128, 256, GEMM_SMEM_2>>>(Wslm, bslm, nullptr, V_, nullptr, nullptr, nullptr);
    mma_gemm<1><<<(S_ + 127) / 128, 256, GEMM_SMEM_1>>>(W2, b2, out, S_, nullptr, slidx, slw);
}

// round 14
// speedup vs baseline: 2.3168x; 1.1493x over previous
#include <cuda_runtime.h>
#include <cuda_fp16.h>
#include <cstdint>

#define B_ 2
#define L_ 64
#define D_ 1024
#define H_ 512
#define S_ 50000
#define V_ 40000
#define KDEG 32
#define R_ 128
#define BN_EPS 1e-5f
#define SLM_SCALE 0.1f
#define NVT 313          // number of v-tiles (ceil(40000/128))

// ---- scratch (device globals; no allocation allowed) ----
__device__ float g_scale[L_];
__device__ float g_shift[L_];
__device__ __half g_h_hi[R_ * H_];
__device__ __half g_h_lo[R_ * H_];
__device__ __half g_vT[(size_t)V_ * R_];   // transposed v (fp16): [V][128]
__device__ int g_vdone;                    // v-tile arrival counter

// ============================================================
// helpers
// ============================================================
__device__ __forceinline__ uint32_t smem_u32(const void* p) {
    uint32_t a;
    asm("{ .reg .u64 t; cvta.to.shared.u64 t, %1; cvt.u32.u64 %0, t; }" : "=r"(a) : "l"(p));
    return a;
}
__device__ __forceinline__ void ldsm_x4(uint32_t* r, uint32_t addr) {
    asm volatile("ldmatrix.sync.aligned.m8n8.x4.shared.b16 {%0,%1,%2,%3}, [%4];"
        : "=r"(r[0]), "=r"(r[1]), "=r"(r[2]), "=r"(r[3]) : "r"(addr));
}
__device__ __forceinline__ void ldsm_x4_t(uint32_t* r, uint32_t addr) {
    asm volatile("ldmatrix.sync.aligned.m8n8.x4.trans.shared.b16 {%0,%1,%2,%3}, [%4];"
        : "=r"(r[0]), "=r"(r[1]), "=r"(r[2]), "=r"(r[3]) : "r"(addr));
}
__device__ __forceinline__ void mma16816(float* c, const uint32_t* a, const uint32_t* b) {
    asm volatile("mma.sync.aligned.m16n8k16.row.col.f32.f16.f16.f32 "
        "{%0,%1,%2,%3}, {%4,%5,%6,%7}, {%8,%9}, {%0,%1,%2,%3};"
        : "+f"(c[0]), "+f"(c[1]), "+f"(c[2]), "+f"(c[3])
        : "r"(a[0]), "r"(a[1]), "r"(a[2]), "r"(a[3]), "r"(b[0]), "r"(b[1]));
}
__device__ __forceinline__ uint32_t pack_h2(float x, float y) {
    __half2 h = __floats2half2_rn(x, y);
    return *reinterpret_cast<uint32_t*>(&h);
}
__device__ __forceinline__ uint32_t pack_l2(float x, float y) {
    __half hx = __float2half_rn(x), hy = __float2half_rn(y);
    return pack_h2(x - __half2float(hx), y - __half2float(hy));
}

// ============================================================
// Kernel 1: BatchNorm stats (+ reset v-arrival counter)
// ============================================================
__global__ void bn_stats_kernel(const float* __restrict__ x,
                                const float* __restrict__ gamma,
                                const float* __restrict__ beta) {
    int l = blockIdx.x;
    int t = threadIdx.x;
    if (l == 0 && t == 0) g_vdone = 0;     // reset for this launch sequence
    float s = 0.f, sq = 0.f;
    for (int b = 0; b < B_; b++) {
        const float* row = x + ((size_t)(b * L_ + l)) * D_;
        for (int d = t; d < D_; d += 256) {
            float v = row[d];
            s += v; sq += v * v;
        }
    }
    __shared__ float sh_s[256], sh_q[256];
    sh_s[t] = s; sh_q[t] = sq;
    __syncthreads();
    for (int off = 128; off > 0; off >>= 1) {
        if (t < off) { sh_s[t] += sh_s[t + off]; sh_q[t] += sh_q[t + off]; }
        __syncthreads();
    }
    if (t == 0) {
        float inv = 1.f / (float)(B_ * D_);
        float mean = sh_s[0] * inv;
        float var = sh_q[0] * inv - mean * mean;
        float sc = gamma[l] * rsqrtf(var + BN_EPS);
        g_scale[l] = sc;
        g_shift[l] = beta[l] - mean * sc;
    }
}

// ============================================================
// Unified fp16 mma.sync GEMM body   C[128,N] = A[128,K]@W[K,N] + bias
// MODE 0: A = BN(x), 3-pass, K=1024, epi = relu+split -> g_h   (h)
// MODE 1: A = g_h hi/lo, 2-pass, K=512, epi = y + fused gather (spin on g_vdone)
// MODE 2: A = g_h hi, 1-pass, K=512, epi = vT fp16 + arrive on g_vdone
// ============================================================
#define A_HI 0
#define A_LO 16384
#define B_HI 32768
#define B_LO 49152
#define SF_PITCH 134
#define PAIR_OFF (128 * SF_PITCH * 4)           // 68608
#define GEMM_SMEM_0 (128 * SF_PITCH * 4)        // 68608
#define GEMM_SMEM_F (PAIR_OFF + 128 * KDEG * 8) // 101376 (fat kernel: max of both paths)

template <int MODE>
__device__ __forceinline__ void gemm_body(
        const float* __restrict__ W, const float* __restrict__ bias,
        float* __restrict__ outparam, int N,
        const float* __restrict__ X,
        const int* __restrict__ sl_idx, const float* __restrict__ sl_w,
        int tileIdx) {
    extern __shared__ char smem[];
    const uint32_t sb = smem_u32(smem);
    const int tid = threadIdx.x;
    const int lane = tid & 31;
    const int wid = tid >> 5;
    const int wm = wid >> 2;         // 0..1
    const int wn = wid & 3;          // 0..3
    const int n0 = tileIdx * 128;

    const int tt = lane >> 3;        // ldmatrix tile group 0..3
    const int lr = lane & 7;
    const uint32_t swz = (uint32_t)lr << 4;

    // MODE 1: stage (idx,w) pairs for this tile's 128 s up front
    if (MODE == 1) {
        uint2* s_pair = (uint2*)(smem + PAIR_OFF);
#pragma unroll
        for (int g = 0; g < 4; g++) {
            int e4 = (g * 256 + tid) * 4;
            int gs = n0 * KDEG + e4;
            int4 i4 = make_int4(0, 0, 0, 0);
            float4 w4 = make_float4(0.f, 0.f, 0.f, 0.f);
            if (gs + 3 < S_ * KDEG) {
                i4 = *(const int4*)(sl_idx + gs);
                w4 = *(const float4*)(sl_w + gs);
            }
            s_pair[e4 + 0] = make_uint2((uint32_t)i4.x, __float_as_uint(w4.x));
            s_pair[e4 + 1] = make_uint2((uint32_t)i4.y, __float_as_uint(w4.y));
            s_pair[e4 + 2] = make_uint2((uint32_t)i4.z, __float_as_uint(w4.z));
            s_pair[e4 + 3] = make_uint2((uint32_t)i4.w, __float_as_uint(w4.w));
        }
    }

    float c[4][4][4];
#pragma unroll
    for (int a = 0; a < 4; a++)
#pragma unroll
        for (int b = 0; b < 4; b++)
#pragma unroll
            for (int d = 0; d < 4; d++) c[a][b][d] = 0.f;

    const int NCH = (MODE == 0) ? 16 : 8;
    for (int ch = 0; ch < NCH; ch++) {
        const int k0 = ch * 64;

        // ---- fill A: [128 m][64 k] fp16, swizzled 128B rows
#pragma unroll
        for (int i = 0; i < 4; i++) {
            int idx = i * 256 + tid;
            int m = idx >> 3, q = idx & 7;
            uint32_t off = (uint32_t)(m * 128 + ((q * 16) ^ ((m & 7) << 4)));
            if (MODE == 0) {
                const float* xs = X + (size_t)m * D_ + k0 + q * 8;
                float4 a0 = *(const float4*)xs;
                float4 a1 = *(const float4*)(xs + 4);
                float sc = g_scale[m & (L_ - 1)];
                float sh = g_shift[m & (L_ - 1)];
                a0.x = fmaf(a0.x, sc, sh); a0.y = fmaf(a0.y, sc, sh);
                a0.z = fmaf(a0.z, sc, sh); a0.w = fmaf(a0.w, sc, sh);
                a1.x = fmaf(a1.x, sc, sh); a1.y = fmaf(a1.y, sc, sh);
                a1.z = fmaf(a1.z, sc, sh); a1.w = fmaf(a1.w, sc, sh);
                uint4 vh, vl;
                vh.x = pack_h2(a0.x, a0.y); vh.y = pack_h2(a0.z, a0.w);
                vh.z = pack_h2(a1.x, a1.y); vh.w = pack_h2(a1.z, a1.w);
                vl.x = pack_l2(a0.x, a0.y); vl.y = pack_l2(a0.z, a0.w);
                vl.z = pack_l2(a1.x, a1.y); vl.w = pack_l2(a1.z, a1.w);
                *(uint4*)(smem + A_HI + off) = vh;
                *(uint4*)(smem + A_LO + off) = vl;
            } else {
                *(uint4*)(smem + A_HI + off) = *(const uint4*)(g_h_hi + (size_t)m * H_ + k0 + q * 8);
                if (MODE == 1)
                    *(uint4*)(smem + A_LO + off) = *(const uint4*)(g_h_lo + (size_t)m * H_ + k0 + q * 8);
            }
        }
        // ---- fill B: [64 k][128 n] fp16 hi (+lo in MODE 0), rows 256B
#pragma unroll
        for (int i = 0; i < 8; i++) {
            int k = (tid >> 5) + i * 8;
            int nl = (tid & 31) * 4;
            int gn = n0 + nl;
            float4 w4 = make_float4(0.f, 0.f, 0.f, 0.f);
            if (gn < N) w4 = *(const float4*)(W + (size_t)(k0 + k) * N + gn);
            uint32_t off = (uint32_t)(k * 256 + ((nl * 2) ^ ((k & 7) << 4)));
            uint2 hv;
            hv.x = pack_h2(w4.x, w4.y); hv.y = pack_h2(w4.z, w4.w);
            *(uint2*)(smem + B_HI + off) = hv;
            if (MODE == 0) {
                uint2 lv;
                lv.x = pack_l2(w4.x, w4.y); lv.y = pack_l2(w4.z, w4.w);
                *(uint2*)(smem + B_LO + off) = lv;
            }
        }
        __syncthreads();

        // ---- consume: 4 k-steps of 16
#pragma unroll
        for (int ks = 0; ks < 4; ks++) {
            uint32_t bh[2][4], bl[2][4];
#pragma unroll
            for (int nt = 0; nt < 2; nt++) {
                uint32_t boff = (uint32_t)((ks * 16 + (tt & 1) * 8 + lr) * 256 +
                                ((wn * 64 + nt * 32 + (tt >> 1) * 16) ^ swz));
                ldsm_x4_t(bh[nt], sb + B_HI + boff);
                if (MODE == 0) ldsm_x4_t(bl[nt], sb + B_LO + boff);
            }
#pragma unroll
            for (int mt = 0; mt < 4; mt++) {
                uint32_t ah[4], al[4];
                uint32_t aoff = (uint32_t)((wm * 64 + mt * 16 + (tt & 1) * 8 + lr) * 128 +
                                ((ks * 32 + (tt >> 1) * 16) ^ swz));
                ldsm_x4(ah, sb + A_HI + aoff);
                if (MODE != 2) ldsm_x4(al, sb + A_LO + aoff);
#pragma unroll
                for (int nt = 0; nt < 2; nt++) {
#pragma unroll
                    for (int f = 0; f < 2; f++) {
                        float* cc = c[mt][nt * 2 + f];
                        mma16816(cc, ah, &bh[nt][2 * f]);
                        if (MODE == 0) mma16816(cc, ah, &bl[nt][2 * f]);
                        if (MODE != 2) mma16816(cc, al, &bh[nt][2 * f]);
                    }
                }
            }
        }
        __syncthreads();
    }

    // ---- epilogue: stage fp32 tile [128 m][SF_PITCH] with bias ----
    float* sf = (float*)smem;
#pragma unroll
    for (int mt = 0; mt < 4; mt++) {
        int m = wm * 64 + mt * 16 + (lane >> 2);
#pragma unroll
        for (int nt = 0; nt < 4; nt++) {
            int nl = wn * 32 + nt * 8 + 2 * (lane & 3);
            int gn = n0 + nl;
            float b0 = (gn < N) ? __ldg(bias + gn) : 0.f;
            float b1 = (gn + 1 < N) ? __ldg(bias + gn + 1) : 0.f;
            *(float2*)(sf + m * SF_PITCH + nl) = make_float2(c[mt][nt][0] + b0, c[mt][nt][1] + b1);
            *(float2*)(sf + (m + 8) * SF_PITCH + nl) = make_float2(c[mt][nt][2] + b0, c[mt][nt][3] + b1);
        }
    }
    __syncthreads();

    if (MODE == 0) {
        // relu + fp16 split -> g_h_hi/lo row-major [m][H_]
        for (int idx = tid; idx < 128 * 64; idx += 256) {
            int m = idx >> 6, np = idx & 63;
            float v0 = fmaxf(sf[m * SF_PITCH + 2 * np], 0.f);
            float v1 = fmaxf(sf[m * SF_PITCH + 2 * np + 1], 0.f);
            uint32_t hp = pack_h2(v0, v1);
            uint32_t lp = pack_l2(v0, v1);
            *(uint32_t*)((char*)g_h_hi + ((size_t)m * H_ + n0 + 2 * np) * 2) = hp;
            *(uint32_t*)((char*)g_h_lo + ((size_t)m * H_ + n0 + 2 * np) * 2) = lp;
        }
    } else if (MODE == 1) {
        // wait for all v-tiles, then fused gather
        if (tid == 0) {
            int v;
            do {
                asm volatile("ld.global.acquire.gpu.s32 %0, [%1];" : "=r"(v) : "l"(&g_vdone));
                if (v < NVT) __nanosleep(64);
            } while (v < NVT);
        }
        __syncthreads();

        const uint2* s_pair = (const uint2*)(smem + PAIR_OFF);
        const int hh = lane >> 4;
        const int hl = lane & 15;
#pragma unroll
        for (int it = 0; it < 8; it++) {
            int sl = it * 16 + wid * 2 + hh;
            float acc[8];
#pragma unroll
            for (int j = 0; j < 8; j++) acc[j] = 0.f;
#pragma unroll 8
            for (int k = 0; k < KDEG; k++) {
                uint2 p = s_pair[sl * KDEG + k];
                float wk = __uint_as_float(p.y);
                uint4 raw = *(const uint4*)(g_vT + (size_t)p.x * R_ + hl * 8);
                uint32_t rw[4] = {raw.x, raw.y, raw.z, raw.w};
#pragma unroll
                for (int q = 0; q < 4; q++) {
                    __half2 hp = *reinterpret_cast<__half2*>(&rw[q]);
                    float2 f = __half22float2(hp);
                    acc[2 * q + 0] = fmaf(wk, f.x, acc[2 * q + 0]);
                    acc[2 * q + 1] = fmaf(wk, f.y, acc[2 * q + 1]);
                }
            }
#pragma unroll
            for (int j = 0; j < 8; j++)
                sf[(hl * 8 + j) * SF_PITCH + sl] += SLM_SCALE * acc[j];
        }
        __syncthreads();
        float* out = outparam;
        for (int idx = tid; idx < 128 * 128; idx += 256) {
            int m = idx >> 7, n = idx & 127;
            int gn = n0 + n;
            if (gn < N) out[(size_t)m * N + gn] = sf[m * SF_PITCH + n];
        }
    } else {
        // write transposed fp16 rows coalesced: vT[n][m], then arrive
        for (int idx = tid; idx < 128 * 64; idx += 256) {
            int n = idx >> 6, mp = idx & 63;
            int gn = n0 + n;
            if (gn < N) {
                float v0 = sf[(2 * mp) * SF_PITCH + n];
                float v1 = sf[(2 * mp + 1) * SF_PITCH + n];
                uint32_t packed = pack_h2(v0, v1);
                *(uint32_t*)((char*)g_vT + ((size_t)gn * R_ + 2 * mp) * 2) = packed;
            }
        }
        __threadfence();
        __syncthreads();
        if (tid == 0) {
            int r;
            asm volatile("atom.global.release.gpu.add.s32 %0, [%1], 1;"
                         : "=r"(r) : "l"(&g_vdone) : "memory");
        }
    }
}

// h = relu(BN(x)@W1+b1) on tensor cores
__global__ void __launch_bounds__(256, 2)
h_gemm(const float* __restrict__ W, const float* __restrict__ bias,
       const float* __restrict__ X) {
    gemm_body<0>(W, bias, nullptr, H_, X, nullptr, nullptr, blockIdx.x);
}

// fat kernel: v-tiles (blocks 0..NVT-1) || y-tiles (blocks NVT..)
__global__ void __launch_bounds__(256, 2)
fat_gemm(const float* __restrict__ Wslm, const float* __restrict__ bslm,
         const float* __restrict__ W2, const float* __restrict__ b2,
         float* __restrict__ out,
         const int* __restrict__ sl_idx, const float* __restrict__ sl_w) {
    if (blockIdx.x < NVT)
        gemm_body<2>(Wslm, bslm, nullptr, V_, nullptr, nullptr, nullptr, blockIdx.x);
    else
        gemm_body<1>(W2, b2, out, S_, nullptr, sl_idx, sl_w, blockIdx.x - NVT);
}

// ============================================================
extern "C" void kernel_launch(void* const* d_in, const int* in_sizes, int n_in,
                              void* d_out, int out_size) {
    const float* x     = (const float*)d_in[0];
    const float* gamma = (const float*)d_in[1];
    const float* beta  = (const float*)d_in[2];
    const float* W1    = (const float*)d_in[3];
    const float* b1    = (const float*)d_in[4];
    const float* W2    = (const float*)d_in[5];
    const float* b2    = (const float*)d_in[6];
    const float* Wslm  = (const float*)d_in[7];
    const float* bslm  = (const float*)d_in[8];
    const float* slw   = (const float*)d_in[9];
    const int*   slidx = (const int*)d_in[10];
    float* out = (float*)d_out;

    cudaFuncSetAttribute(h_gemm, cudaFuncAttributeMaxDynamicSharedMemorySize, GEMM_SMEM_0);
    cudaFuncSetAttribute(fat_gemm, cudaFuncAttributeMaxDynamicSharedMemorySize, GEMM_SMEM_F);

    bn_stats_kernel<<<L_, 256>>>(x, gamma, beta);
    h_gemm<<<H_ / 128, 256, GEMM_SMEM_0>>>(W1, b1, x);
    fat_gemm<<<NVT + (S_ + 127) / 128, 256, GEMM_SMEM_F>>>(Wslm, bslm, W2, b2, out, slidx, slw);
}

// round 15
// speedup vs baseline: 2.4806x; 1.0707x over previous
#include <cuda_runtime.h>
#include <cuda_fp16.h>
#include <cstdint>

#define B_ 2
#define L_ 64
#define D_ 1024
#define H_ 512
#define S_ 50000
#define V_ 40000
#define KDEG 32
#define R_ 128
#define BN_EPS 1e-5f
#define SLM_SCALE 0.1f
#define NVT 313          // number of v-tiles (ceil(40000/128))

// ---- scratch (device globals; no allocation allowed) ----
__device__ float g_scale[L_];
__device__ float g_shift[L_];
__device__ __half g_h_hi[R_ * H_];
__device__ __half g_h_lo[R_ * H_];
__device__ __half g_vT[(size_t)V_ * R_];   // transposed v (fp16): [V][128]
__device__ int g_vdone;                    // v-tile arrival counter

// ============================================================
// helpers
// ============================================================
__device__ __forceinline__ uint32_t smem_u32(const void* p) {
    uint32_t a;
    asm("{ .reg .u64 t; cvta.to.shared.u64 t, %1; cvt.u32.u64 %0, t; }" : "=r"(a) : "l"(p));
    return a;
}
__device__ __forceinline__ void ldsm_x4(uint32_t* r, uint32_t addr) {
    asm volatile("ldmatrix.sync.aligned.m8n8.x4.shared.b16 {%0,%1,%2,%3}, [%4];"
        : "=r"(r[0]), "=r"(r[1]), "=r"(r[2]), "=r"(r[3]) : "r"(addr));
}
__device__ __forceinline__ void ldsm_x4_t(uint32_t* r, uint32_t addr) {
    asm volatile("ldmatrix.sync.aligned.m8n8.x4.trans.shared.b16 {%0,%1,%2,%3}, [%4];"
        : "=r"(r[0]), "=r"(r[1]), "=r"(r[2]), "=r"(r[3]) : "r"(addr));
}
__device__ __forceinline__ void mma16816(float* c, const uint32_t* a, const uint32_t* b) {
    asm volatile("mma.sync.aligned.m16n8k16.row.col.f32.f16.f16.f32 "
        "{%0,%1,%2,%3}, {%4,%5,%6,%7}, {%8,%9}, {%0,%1,%2,%3};"
        : "+f"(c[0]), "+f"(c[1]), "+f"(c[2]), "+f"(c[3])
        : "r"(a[0]), "r"(a[1]), "r"(a[2]), "r"(a[3]), "r"(b[0]), "r"(b[1]));
}
__device__ __forceinline__ uint32_t pack_h2(float x, float y) {
    __half2 h = __floats2half2_rn(x, y);
    return *reinterpret_cast<uint32_t*>(&h);
}
__device__ __forceinline__ uint32_t pack_l2(float x, float y) {
    __half hx = __float2half_rn(x), hy = __float2half_rn(y);
    return pack_h2(x - __half2float(hx), y - __half2float(hy));
}
__device__ __forceinline__ void cp_async16(uint32_t dst, const void* src, uint32_t sz) {
    asm volatile("cp.async.cg.shared.global [%0], [%1], 16, %2;"
        :: "r"(dst), "l"(src), "r"(sz));
}

// ============================================================
// Kernel 1: BatchNorm stats (+ reset v-arrival counter)
// ============================================================
__global__ void bn_stats_kernel(const float* __restrict__ x,
                                const float* __restrict__ gamma,
                                const float* __restrict__ beta) {
    int l = blockIdx.x;
    int t = threadIdx.x;
    if (l == 0 && t == 0) g_vdone = 0;
    float s = 0.f, sq = 0.f;
    for (int b = 0; b < B_; b++) {
        const float* row = x + ((size_t)(b * L_ + l)) * D_;
        for (int d = t; d < D_; d += 256) {
            float v = row[d];
            s += v; sq += v * v;
        }
    }
    __shared__ float sh_s[256], sh_q[256];
    sh_s[t] = s; sh_q[t] = sq;
    __syncthreads();
    for (int off = 128; off > 0; off >>= 1) {
        if (t < off) { sh_s[t] += sh_s[t + off]; sh_q[t] += sh_q[t + off]; }
        __syncthreads();
    }
    if (t == 0) {
        float inv = 1.f / (float)(B_ * D_);
        float mean = sh_s[0] * inv;
        float var = sh_q[0] * inv - mean * mean;
        float sc = gamma[l] * rsqrtf(var + BN_EPS);
        g_scale[l] = sc;
        g_shift[l] = beta[l] - mean * sc;
    }
}

// ============================================================
// Unified fp16 mma.sync GEMM body   C[128,N] = A[128,K]@W[K,N] + bias
// MODE 0: A = BN(x), 3-pass, K=1024, direct LDG fill (4 CTAs only)
// MODE 1: A = g_h hi/lo, 2-pass, cp.async-pipelined W, epi = y + fused gather
// MODE 2: A = g_h hi, 1-pass, cp.async-pipelined W, epi = vT fp16 + arrive
// ============================================================
#define A_HI 0
#define A_LO 16384
#define B_HI 32768
#define B_LO 49152                              // MODE 0 only (aliases B_STG)
#define B_STG 49152                             // 32KB fp32 staging (MODE 1/2)
#define SF_PITCH 134
#define PAIR_OFF 81920                          // 16KB packed pairs (MODE 1)
#define GEMM_SMEM_0 (128 * SF_PITCH * 4)        // 68608
#define GEMM_SMEM_F (PAIR_OFF + 128 * KDEG * 4) // 81920 + 16384 = 98304

template <int MODE>
__device__ __forceinline__ void gemm_body(
        const float* __restrict__ W, const float* __restrict__ bias,
        float* __restrict__ outparam, int N,
        const float* __restrict__ X,
        const int* __restrict__ sl_idx, const float* __restrict__ sl_w,
        int tileIdx) {
    extern __shared__ char smem[];
    const uint32_t sb = smem_u32(smem);
    const int tid = threadIdx.x;
    const int lane = tid & 31;
    const int wid = tid >> 5;
    const int wm = wid >> 2;         // 0..1
    const int wn = wid & 3;          // 0..3
    const int n0 = tileIdx * 128;

    const int tt = lane >> 3;
    const int lr = lane & 7;
    const uint32_t swz = (uint32_t)lr << 4;

    // MODE 1: stage packed (w_fp16<<16 | idx_u16) pairs up front
    if (MODE == 1) {
        uint32_t* s_pair = (uint32_t*)(smem + PAIR_OFF);
#pragma unroll
        for (int g = 0; g < 4; g++) {
            int e4 = (g * 256 + tid) * 4;
            int gs = n0 * KDEG + e4;
            int4 i4 = make_int4(0, 0, 0, 0);
            float4 w4 = make_float4(0.f, 0.f, 0.f, 0.f);
            if (gs + 3 < S_ * KDEG) {
                i4 = *(const int4*)(sl_idx + gs);
                w4 = *(const float4*)(sl_w + gs);
            }
            s_pair[e4 + 0] = ((uint32_t)__half_as_ushort(__float2half_rn(w4.x)) << 16) | ((uint32_t)i4.x & 0xFFFF);
            s_pair[e4 + 1] = ((uint32_t)__half_as_ushort(__float2half_rn(w4.y)) << 16) | ((uint32_t)i4.y & 0xFFFF);
            s_pair[e4 + 2] = ((uint32_t)__half_as_ushort(__float2half_rn(w4.z)) << 16) | ((uint32_t)i4.z & 0xFFFF);
            s_pair[e4 + 3] = ((uint32_t)__half_as_ushort(__float2half_rn(w4.w)) << 16) | ((uint32_t)i4.w & 0xFFFF);
        }
    }

    float c[4][4][4];
#pragma unroll
    for (int a = 0; a < 4; a++)
#pragma unroll
        for (int b = 0; b < 4; b++)
#pragma unroll
            for (int d = 0; d < 4; d++) c[a][b][d] = 0.f;

    const int NCH = (MODE == 0) ? 16 : 8;

    // prologue: cp.async W chunk 0 into staging (MODE 1/2)
    if (MODE != 0) {
#pragma unroll
        for (int i = 0; i < 8; i++) {
            int k = (tid >> 5) + i * 8;
            int nl = (tid & 31) * 4;
            int gn = n0 + nl;
            const float* src = (gn < N) ? (W + (size_t)k * N + gn) : W;
            cp_async16(sb + B_STG + (uint32_t)(k * 512 + nl * 4), src, (gn < N) ? 16u : 0u);
        }
        asm volatile("cp.async.commit_group;" ::: "memory");
    }

    for (int ch = 0; ch < NCH; ch++) {
        const int k0 = ch * 64;

        if (MODE != 0) {
            asm volatile("cp.async.wait_group 0;" ::: "memory");
            __syncthreads();    // staging(ch) ready; consume(ch-1) finished
        }

        // ---- fill A: [128 m][64 k] fp16, swizzled 128B rows
#pragma unroll
        for (int i = 0; i < 4; i++) {
            int idx = i * 256 + tid;
            int m = idx >> 3, q = idx & 7;
            uint32_t off = (uint32_t)(m * 128 + ((q * 16) ^ ((m & 7) << 4)));
            if (MODE == 0) {
                const float* xs = X + (size_t)m * D_ + k0 + q * 8;
                float4 a0 = *(const float4*)xs;
                float4 a1 = *(const float4*)(xs + 4);
                float sc = g_scale[m & (L_ - 1)];
                float sh = g_shift[m & (L_ - 1)];
                a0.x = fmaf(a0.x, sc, sh); a0.y = fmaf(a0.y, sc, sh);
                a0.z = fmaf(a0.z, sc, sh); a0.w = fmaf(a0.w, sc, sh);
                a1.x = fmaf(a1.x, sc, sh); a1.y = fmaf(a1.y, sc, sh);
                a1.z = fmaf(a1.z, sc, sh); a1.w = fmaf(a1.w, sc, sh);
                uint4 vh, vl;
                vh.x = pack_h2(a0.x, a0.y); vh.y = pack_h2(a0.z, a0.w);
                vh.z = pack_h2(a1.x, a1.y); vh.w = pack_h2(a1.z, a1.w);
                vl.x = pack_l2(a0.x, a0.y); vl.y = pack_l2(a0.z, a0.w);
                vl.z = pack_l2(a1.x, a1.y); vl.w = pack_l2(a1.z, a1.w);
                *(uint4*)(smem + A_HI + off) = vh;
                *(uint4*)(smem + A_LO + off) = vl;
            } else {
                *(uint4*)(smem + A_HI + off) = *(const uint4*)(g_h_hi + (size_t)m * H_ + k0 + q * 8);
                if (MODE == 1)
                    *(uint4*)(smem + A_LO + off) = *(const uint4*)(g_h_lo + (size_t)m * H_ + k0 + q * 8);
            }
        }

        // ---- fill B
        if (MODE == 0) {
            // direct LDG + convert (hi + lo)
#pragma unroll
            for (int i = 0; i < 8; i++) {
                int k = (tid >> 5) + i * 8;
                int nl = (tid & 31) * 4;
                int gn = n0 + nl;
                float4 w4 = make_float4(0.f, 0.f, 0.f, 0.f);
                if (gn < N) w4 = *(const float4*)(W + (size_t)(k0 + k) * N + gn);
                uint32_t off = (uint32_t)(k * 256 + ((nl * 2) ^ ((k & 7) << 4)));
                uint2 hv, lv;
                hv.x = pack_h2(w4.x, w4.y); hv.y = pack_h2(w4.z, w4.w);
                lv.x = pack_l2(w4.x, w4.y); lv.y = pack_l2(w4.z, w4.w);
                *(uint2*)(smem + B_HI + off) = hv;
                *(uint2*)(smem + B_LO + off) = lv;
            }
        } else {
            // convert staging fp32 -> B_HI fp16 swizzled (smem -> smem)
#pragma unroll
            for (int i = 0; i < 8; i++) {
                int k = (tid >> 5) + i * 8;
                int nl = (tid & 31) * 4;
                float4 w4 = *(const float4*)(smem + B_STG + k * 512 + nl * 4);
                uint32_t off = (uint32_t)(k * 256 + ((nl * 2) ^ ((k & 7) << 4)));
                uint2 hv;
                hv.x = pack_h2(w4.x, w4.y); hv.y = pack_h2(w4.z, w4.w);
                *(uint2*)(smem + B_HI + off) = hv;
            }
        }
        __syncthreads();    // B_HI/A ready; staging free

        // issue next chunk's W loads — overlap with consume below
        if (MODE != 0 && ch + 1 < NCH) {
            const int kn = (ch + 1) * 64;
#pragma unroll
            for (int i = 0; i < 8; i++) {
                int k = (tid >> 5) + i * 8;
                int nl = (tid & 31) * 4;
                int gn = n0 + nl;
                const float* src = (gn < N) ? (W + (size_t)(kn + k) * N + gn) : W;
                cp_async16(sb + B_STG + (uint32_t)(k * 512 + nl * 4), src, (gn < N) ? 16u : 0u);
            }
            asm volatile("cp.async.commit_group;" ::: "memory");
        }

        // ---- consume: 4 k-steps of 16
#pragma unroll
        for (int ks = 0; ks < 4; ks++) {
            uint32_t bh[2][4], bl[2][4];
#pragma unroll
            for (int nt = 0; nt < 2; nt++) {
                uint32_t boff = (uint32_t)((ks * 16 + (tt & 1) * 8 + lr) * 256 +
                                ((wn * 64 + nt * 32 + (tt >> 1) * 16) ^ swz));
                ldsm_x4_t(bh[nt], sb + B_HI + boff);
                if (MODE == 0) ldsm_x4_t(bl[nt], sb + B_LO + boff);
            }
#pragma unroll
            for (int mt = 0; mt < 4; mt++) {
                uint32_t ah[4], al[4];
                uint32_t aoff = (uint32_t)((wm * 64 + mt * 16 + (tt & 1) * 8 + lr) * 128 +
                                ((ks * 32 + (tt >> 1) * 16) ^ swz));
                ldsm_x4(ah, sb + A_HI + aoff);
                if (MODE != 2) ldsm_x4(al, sb + A_LO + aoff);
#pragma unroll
                for (int nt = 0; nt < 2; nt++) {
#pragma unroll
                    for (int f = 0; f < 2; f++) {
                        float* cc = c[mt][nt * 2 + f];
                        mma16816(cc, ah, &bh[nt][2 * f]);
                        if (MODE == 0) mma16816(cc, ah, &bl[nt][2 * f]);
                        if (MODE != 2) mma16816(cc, al, &bh[nt][2 * f]);
                    }
                }
            }
        }
        if (MODE == 0) __syncthreads();   // MODE!=0 syncs at loop top
    }
    if (MODE != 0) __syncthreads();       // last consume done before epilogue overwrites smem

    // ---- epilogue: stage fp32 tile [128 m][SF_PITCH] with bias ----
    float* sf = (float*)smem;
#pragma unroll
    for (int mt = 0; mt < 4; mt++) {
        int m = wm * 64 + mt * 16 + (lane >> 2);
#pragma unroll
        for (int nt = 0; nt < 4; nt++) {
            int nl = wn * 32 + nt * 8 + 2 * (lane & 3);
            int gn = n0 + nl;
            float b0 = (gn < N) ? __ldg(bias + gn) : 0.f;
            float b1 = (gn + 1 < N) ? __ldg(bias + gn + 1) : 0.f;
            *(float2*)(sf + m * SF_PITCH + nl) = make_float2(c[mt][nt][0] + b0, c[mt][nt][1] + b1);
            *(float2*)(sf + (m + 8) * SF_PITCH + nl) = make_float2(c[mt][nt][2] + b0, c[mt][nt][3] + b1);
        }
    }
    __syncthreads();

    if (MODE == 0) {
        for (int idx = tid; idx < 128 * 64; idx += 256) {
            int m = idx >> 6, np = idx & 63;
            float v0 = fmaxf(sf[m * SF_PITCH + 2 * np], 0.f);
            float v1 = fmaxf(sf[m * SF_PITCH + 2 * np + 1], 0.f);
            uint32_t hp = pack_h2(v0, v1);
            uint32_t lp = pack_l2(v0, v1);
            *(uint32_t*)((char*)g_h_hi + ((size_t)m * H_ + n0 + 2 * np) * 2) = hp;
            *(uint32_t*)((char*)g_h_lo + ((size_t)m * H_ + n0 + 2 * np) * 2) = lp;
        }
    } else if (MODE == 1) {
        // wait for all v-tiles, then fused gather
        if (tid == 0) {
            int v;
            do {
                asm volatile("ld.global.acquire.gpu.s32 %0, [%1];" : "=r"(v) : "l"(&g_vdone));
                if (v < NVT) __nanosleep(64);
            } while (v < NVT);
        }
        __syncthreads();

        const uint32_t* s_pair = (const uint32_t*)(smem + PAIR_OFF);
        const int hh = lane >> 4;
        const int hl = lane & 15;
#pragma unroll
        for (int it = 0; it < 8; it++) {
            int sl = it * 16 + wid * 2 + hh;
            float acc[8];
#pragma unroll
            for (int j = 0; j < 8; j++) acc[j] = 0.f;
#pragma unroll 8
            for (int k = 0; k < KDEG; k++) {
                uint32_t p = s_pair[sl * KDEG + k];
                float wk = __half2float(__ushort_as_half((unsigned short)(p >> 16)));
                uint32_t jj = p & 0xFFFFu;
                uint4 raw = *(const uint4*)(g_vT + (size_t)jj * R_ + hl * 8);
                uint32_t rw[4] = {raw.x, raw.y, raw.z, raw.w};
#pragma unroll
                for (int q = 0; q < 4; q++) {
                    __half2 hp = *reinterpret_cast<__half2*>(&rw[q]);
                    float2 f = __half22float2(hp);
                    acc[2 * q + 0] = fmaf(wk, f.x, acc[2 * q + 0]);
                    acc[2 * q + 1] = fmaf(wk, f.y, acc[2 * q + 1]);
                }
            }
#pragma unroll
            for (int j = 0; j < 8; j++)
                sf[(hl * 8 + j) * SF_PITCH + sl] += SLM_SCALE * acc[j];
        }
        __syncthreads();
        float* out = outparam;
        for (int idx = tid; idx < 128 * 128; idx += 256) {
            int m = idx >> 7, n = idx & 127;
            int gn = n0 + n;
            if (gn < N) out[(size_t)m * N + gn] = sf[m * SF_PITCH + n];
        }
    } else {
        for (int idx = tid; idx < 128 * 64; idx += 256) {
            int n = idx >> 6, mp = idx & 63;
            int gn = n0 + n;
            if (gn < N) {
                float v0 = sf[(2 * mp) * SF_PITCH + n];
                float v1 = sf[(2 * mp + 1) * SF_PITCH + n];
                uint32_t packed = pack_h2(v0, v1);
                *(uint32_t*)((char*)g_vT + ((size_t)gn * R_ + 2 * mp) * 2) = packed;
            }
        }
        __threadfence();
        __syncthreads();
        if (tid == 0) {
            int r;
            asm volatile("atom.global.release.gpu.add.s32 %0, [%1], 1;"
                         : "=r"(r) : "l"(&g_vdone) : "memory");
        }
    }
}

// h = relu(BN(x)@W1+b1) on tensor cores
__global__ void __launch_bounds__(256, 2)
h_gemm(const float* __restrict__ W, const float* __restrict__ bias,
       const float* __restrict__ X) {
    gemm_body<0>(W, bias, nullptr, H_, X, nullptr, nullptr, blockIdx.x);
}

// fat kernel: v-tiles (blocks 0..NVT-1) || y-tiles (blocks NVT..)
__global__ void __launch_bounds__(256, 2)
fat_gemm(const float* __restrict__ Wslm, const float* __restrict__ bslm,
         const float* __restrict__ W2, const float* __restrict__ b2,
         float* __restrict__ out,
         const int* __restrict__ sl_idx, const float* __restrict__ sl_w) {
    if (blockIdx.x < NVT)
        gemm_body<2>(Wslm, bslm, nullptr, V_, nullptr, nullptr, nullptr, blockIdx.x);
    else
        gemm_body<1>(W2, b2, out, S_, nullptr, sl_idx, sl_w, blockIdx.x - NVT);
}

// ============================================================
extern "C" void kernel_launch(void* const* d_in, const int* in_sizes, int n_in,
                              void* d_out, int out_size) {
    const float* x     = (const float*)d_in[0];
    const float* gamma = (const float*)d_in[1];
    const float* beta  = (const float*)d_in[2];
    const float* W1    = (const float*)d_in[3];
    const float* b1    = (const float*)d_in[4];
    const float* W2    = (const float*)d_in[5];
    const float* b2    = (const float*)d_in[6];
    const float* Wslm  = (const float*)d_in[7];
    const float* bslm  = (const float*)d_in[8];
    const float* slw   = (const float*)d_in[9];
    const int*   slidx = (const int*)d_in[10];
    float* out = (float*)d_out;

    cudaFuncSetAttribute(h_gemm, cudaFuncAttributeMaxDynamicSharedMemorySize, GEMM_SMEM_0);
    cudaFuncSetAttribute(fat_gemm, cudaFuncAttributeMaxDynamicSharedMemorySize, GEMM_SMEM_F);

    bn_stats_kernel<<<L_, 256>>>(x, gamma, beta);
    h_gemm<<<H_ / 128, 256, GEMM_SMEM_0>>>(W1, b1, x);
    fat_gemm<<<NVT + (S_ + 127) / 128, 256, GEMM_SMEM_F>>>(Wslm, bslm, W2, b2, out, slidx, slw);
}

// round 16
// speedup vs baseline: 2.5331x; 1.0212x over previous
#include <cuda_runtime.h>
#include <cuda_fp16.h>
#include <cstdint>

#define B_ 2
#define L_ 64
#define D_ 1024
#define H_ 512
#define S_ 50000
#define V_ 40000
#define KDEG 32
#define R_ 128
#define BN_EPS 1e-5f
#define SLM_SCALE 0.1f
#define NVT 313                       // v-tiles
#define NYT ((S_ + 127) / 128)        // 391 y-tiles
#define NTILES (NVT + NYT)            // 704
#define PGRID 296                     // persistent CTAs (= co-resident set)

// ---- scratch (device globals; no allocation allowed) ----
__device__ float g_scale[L_];
__device__ float g_shift[L_];
__device__ __half g_h_hi[R_ * H_];
__device__ __half g_h_lo[R_ * H_];
__device__ __half g_vT[(size_t)V_ * R_];
__device__ int g_vdone;

// ============================================================
// helpers
// ============================================================
__device__ __forceinline__ uint32_t smem_u32(const void* p) {
    uint32_t a;
    asm("{ .reg .u64 t; cvta.to.shared.u64 t, %1; cvt.u32.u64 %0, t; }" : "=r"(a) : "l"(p));
    return a;
}
__device__ __forceinline__ void ldsm_x4(uint32_t* r, uint32_t addr) {
    asm volatile("ldmatrix.sync.aligned.m8n8.x4.shared.b16 {%0,%1,%2,%3}, [%4];"
        : "=r"(r[0]), "=r"(r[1]), "=r"(r[2]), "=r"(r[3]) : "r"(addr));
}
__device__ __forceinline__ void ldsm_x4_t(uint32_t* r, uint32_t addr) {
    asm volatile("ldmatrix.sync.aligned.m8n8.x4.trans.shared.b16 {%0,%1,%2,%3}, [%4];"
        : "=r"(r[0]), "=r"(r[1]), "=r"(r[2]), "=r"(r[3]) : "r"(addr));
}
__device__ __forceinline__ void mma16816(float* c, const uint32_t* a, const uint32_t* b) {
    asm volatile("mma.sync.aligned.m16n8k16.row.col.f32.f16.f16.f32 "
        "{%0,%1,%2,%3}, {%4,%5,%6,%7}, {%8,%9}, {%0,%1,%2,%3};"
        : "+f"(c[0]), "+f"(c[1]), "+f"(c[2]), "+f"(c[3])
        : "r"(a[0]), "r"(a[1]), "r"(a[2]), "r"(a[3]), "r"(b[0]), "r"(b[1]));
}
__device__ __forceinline__ uint32_t pack_h2(float x, float y) {
    __half2 h = __floats2half2_rn(x, y);
    return *reinterpret_cast<uint32_t*>(&h);
}
__device__ __forceinline__ uint32_t pack_l2(float x, float y) {
    __half hx = __float2half_rn(x), hy = __float2half_rn(y);
    return pack_h2(x - __half2float(hx), y - __half2float(hy));
}
__device__ __forceinline__ void cp_async16(uint32_t dst, const void* src, uint32_t sz) {
    asm volatile("cp.async.cg.shared.global [%0], [%1], 16, %2;"
        :: "r"(dst), "l"(src), "r"(sz));
}
#define CP_COMMIT() asm volatile("cp.async.commit_group;" ::: "memory")
#define CP_WAIT(n)  asm volatile("cp.async.wait_group %0;" :: "n"(n) : "memory")

// ============================================================
// Kernel 1: BatchNorm stats (+ reset v counter)
// ============================================================
__global__ void bn_stats_kernel(const float* __restrict__ x,
                                const float* __restrict__ gamma,
                                const float* __restrict__ beta) {
    int l = blockIdx.x;
    int t = threadIdx.x;
    if (l == 0 && t == 0) g_vdone = 0;
    float s = 0.f, sq = 0.f;
    for (int b = 0; b < B_; b++) {
        const float* row = x + ((size_t)(b * L_ + l)) * D_;
        for (int d = t; d < D_; d += 256) {
            float v = row[d];
            s += v; sq += v * v;
        }
    }
    __shared__ float sh_s[256], sh_q[256];
    sh_s[t] = s; sh_q[t] = sq;
    __syncthreads();
    for (int off = 128; off > 0; off >>= 1) {
        if (t < off) { sh_s[t] += sh_s[t + off]; sh_q[t] += sh_q[t + off]; }
        __syncthreads();
    }
    if (t == 0) {
        float inv = 1.f / (float)(B_ * D_);
        float mean = sh_s[0] * inv;
        float var = sh_q[0] * inv - mean * mean;
        float sc = gamma[l] * rsqrtf(var + BN_EPS);
        g_scale[l] = sc;
        g_shift[l] = beta[l] - mean * sc;
    }
}

// ============================================================
// Kernel 2: h = relu(BN(x)@W1+b1), 3-pass fp16 (4 CTAs, proven R13 body)
// ============================================================
#define HA_HI 0
#define HA_LO 16384
#define HB_HI 32768
#define HB_LO 49152
#define SF_PITCH 134
#define H_SMEM (128 * SF_PITCH * 4)     // 68608

__global__ void __launch_bounds__(256, 2)
h_gemm(const float* __restrict__ W, const float* __restrict__ bias,
       const float* __restrict__ X) {
    extern __shared__ char smem[];
    const uint32_t sb = smem_u32(smem);
    const int tid = threadIdx.x;
    const int lane = tid & 31;
    const int wid = tid >> 5;
    const int wm = wid >> 2, wn = wid & 3;
    const int n0 = blockIdx.x * 128;
    const int tt = lane >> 3, lr = lane & 7;
    const uint32_t swz = (uint32_t)lr << 4;
    const int N = H_;

    float c[4][4][4];
#pragma unroll
    for (int a = 0; a < 4; a++)
#pragma unroll
        for (int b = 0; b < 4; b++)
#pragma unroll
            for (int d = 0; d < 4; d++) c[a][b][d] = 0.f;

    for (int ch = 0; ch < 16; ch++) {
        const int k0 = ch * 64;
#pragma unroll
        for (int i = 0; i < 4; i++) {
            int idx = i * 256 + tid;
            int m = idx >> 3, q = idx & 7;
            uint32_t off = (uint32_t)(m * 128 + ((q * 16) ^ ((m & 7) << 4)));
            const float* xs = X + (size_t)m * D_ + k0 + q * 8;
            float4 a0 = *(const float4*)xs;
            float4 a1 = *(const float4*)(xs + 4);
            float sc = g_scale[m & (L_ - 1)];
            float sh = g_shift[m & (L_ - 1)];
            a0.x = fmaf(a0.x, sc, sh); a0.y = fmaf(a0.y, sc, sh);
            a0.z = fmaf(a0.z, sc, sh); a0.w = fmaf(a0.w, sc, sh);
            a1.x = fmaf(a1.x, sc, sh); a1.y = fmaf(a1.y, sc, sh);
            a1.z = fmaf(a1.z, sc, sh); a1.w = fmaf(a1.w, sc, sh);
            uint4 vh, vl;
            vh.x = pack_h2(a0.x, a0.y); vh.y = pack_h2(a0.z, a0.w);
            vh.z = pack_h2(a1.x, a1.y); vh.w = pack_h2(a1.z, a1.w);
            vl.x = pack_l2(a0.x, a0.y); vl.y = pack_l2(a0.z, a0.w);
            vl.z = pack_l2(a1.x, a1.y); vl.w = pack_l2(a1.z, a1.w);
            *(uint4*)(smem + HA_HI + off) = vh;
            *(uint4*)(smem + HA_LO + off) = vl;
        }
#pragma unroll
        for (int i = 0; i < 8; i++) {
            int k = (tid >> 5) + i * 8;
            int nl = (tid & 31) * 4;
            float4 w4 = *(const float4*)(W + (size_t)(k0 + k) * N + n0 + nl);
            uint32_t off = (uint32_t)(k * 256 + ((nl * 2) ^ ((k & 7) << 4)));
            uint2 hv, lv;
            hv.x = pack_h2(w4.x, w4.y); hv.y = pack_h2(w4.z, w4.w);
            lv.x = pack_l2(w4.x, w4.y); lv.y = pack_l2(w4.z, w4.w);
            *(uint2*)(smem + HB_HI + off) = hv;
            *(uint2*)(smem + HB_LO + off) = lv;
        }
        __syncthreads();
#pragma unroll
        for (int ks = 0; ks < 4; ks++) {
            uint32_t bh[2][4], bl[2][4];
#pragma unroll
            for (int nt = 0; nt < 2; nt++) {
                uint32_t boff = (uint32_t)((ks * 16 + (tt & 1) * 8 + lr) * 256 +
                                ((wn * 64 + nt * 32 + (tt >> 1) * 16) ^ swz));
                ldsm_x4_t(bh[nt], sb + HB_HI + boff);
                ldsm_x4_t(bl[nt], sb + HB_LO + boff);
            }
#pragma unroll
            for (int mt = 0; mt < 4; mt++) {
                uint32_t ah[4], al[4];
                uint32_t aoff = (uint32_t)((wm * 64 + mt * 16 + (tt & 1) * 8 + lr) * 128 +
                                ((ks * 32 + (tt >> 1) * 16) ^ swz));
                ldsm_x4(ah, sb + HA_HI + aoff);
                ldsm_x4(al, sb + HA_LO + aoff);
#pragma unroll
                for (int nt = 0; nt < 2; nt++) {
#pragma unroll
                    for (int f = 0; f < 2; f++) {
                        float* cc = c[mt][nt * 2 + f];
                        mma16816(cc, ah, &bh[nt][2 * f]);
                        mma16816(cc, ah, &bl[nt][2 * f]);
                        mma16816(cc, al, &bh[nt][2 * f]);
                    }
                }
            }
        }
        __syncthreads();
    }

    float* sf = (float*)smem;
#pragma unroll
    for (int mt = 0; mt < 4; mt++) {
        int m = wm * 64 + mt * 16 + (lane >> 2);
#pragma unroll
        for (int nt = 0; nt < 4; nt++) {
            int nl = wn * 32 + nt * 8 + 2 * (lane & 3);
            float b0 = __ldg(bias + n0 + nl), b1 = __ldg(bias + n0 + nl + 1);
            *(float2*)(sf + m * SF_PITCH + nl) = make_float2(c[mt][nt][0] + b0, c[mt][nt][1] + b1);
            *(float2*)(sf + (m + 8) * SF_PITCH + nl) = make_float2(c[mt][nt][2] + b0, c[mt][nt][3] + b1);
        }
    }
    __syncthreads();
    for (int idx = tid; idx < 128 * 64; idx += 256) {
        int m = idx >> 6, np = idx & 63;
        float v0 = fmaxf(sf[m * SF_PITCH + 2 * np], 0.f);
        float v1 = fmaxf(sf[m * SF_PITCH + 2 * np + 1], 0.f);
        *(uint32_t*)((char*)g_h_hi + ((size_t)m * H_ + n0 + 2 * np) * 2) = pack_h2(v0, v1);
        *(uint32_t*)((char*)g_h_lo + ((size_t)m * H_ + n0 + 2 * np) * 2) = pack_l2(v0, v1);
    }
}

// ============================================================
// Persistent fat kernel: BK=32, 16 chunks, 3-deep async rings.
// MODE 1 (y): 2-pass (A hi+lo), epilogue y + fused gather
// MODE 2 (v): 1-pass (A hi),    epilogue vT fp16 + arrive
// smem: STG (W fp32) 3x16K @0 | A ring 3x16K @49152 (hi+0,lo+8192) |
//       BHI 2x8K @98304 | total 114688; epilogue reuses: sf@0, pairs@69632
// ============================================================
#define STG_OFF 0
#define STG_SZ 16384
#define AR_OFF 49152
#define AR_SZ 16384
#define BHI_OFF 98304
#define BHI_SZ 8192
#define PAIR_EPI 69632
#define FAT_SMEM 114688

template <int MODE>
__device__ __forceinline__ void issue_chunk32(char* smem, uint32_t sb, int ch,
                                              const float* __restrict__ W, int N, int n0) {
    const int tid = threadIdx.x;
    const int k0 = ch * 32;
    const uint32_t stg = sb + STG_OFF + (ch % 3) * STG_SZ;
    const uint32_t ar = sb + AR_OFF + (ch % 3) * AR_SZ;
    // W: 32 rows x 512B fp32
#pragma unroll
    for (int i = 0; i < 4; i++) {
        int k = (tid >> 5) + i * 8;
        int nl = (tid & 31) * 4;
        int gn = n0 + nl;
        const float* src = (gn < N) ? (W + (size_t)(k0 + k) * N + gn) : W;
        cp_async16(stg + (uint32_t)(k * 512 + nl * 4), src, (gn < N) ? 16u : 0u);
    }
    // A: 128m x 32k fp16, 64B rows, XOR (m&3)<<4
#pragma unroll
    for (int i = 0; i < 2; i++) {
        int u = i * 256 + tid;
        int m = u >> 2, q = u & 3;
        uint32_t off = (uint32_t)(m * 64 + ((q * 16) ^ ((m & 3) << 4)));
        cp_async16(ar + off, g_h_hi + (size_t)m * H_ + k0 + q * 8, 16);
        if (MODE == 1)
            cp_async16(ar + 8192 + off, g_h_lo + (size_t)m * H_ + k0 + q * 8, 16);
    }
    CP_COMMIT();
}

template <int MODE>
__device__ __forceinline__ void tile_body(
        const float* __restrict__ W, const float* __restrict__ bias,
        float* __restrict__ outparam, int N,
        const int* __restrict__ sl_idx, const float* __restrict__ sl_w,
        int tileIdx) {
    extern __shared__ char smem[];
    const uint32_t sb = smem_u32(smem);
    const int tid = threadIdx.x;
    const int lane = tid & 31;
    const int wid = tid >> 5;
    const int wm = wid >> 2, wn = wid & 3;
    const int n0 = tileIdx * 128;
    const int tt = lane >> 3, lr = lane & 7;
    const uint32_t swz = (uint32_t)lr << 4;

    float c[4][4][4];
#pragma unroll
    for (int a = 0; a < 4; a++)
#pragma unroll
        for (int b = 0; b < 4; b++)
#pragma unroll
            for (int d = 0; d < 4; d++) c[a][b][d] = 0.f;

    // prologue: 2 chunks in flight
    issue_chunk32<MODE>(smem, sb, 0, W, N, n0);
    issue_chunk32<MODE>(smem, sb, 1, W, N, n0);

    for (int ch = 0; ch < 16; ch++) {
        if (ch < 15) { CP_WAIT(1); } else { CP_WAIT(0); }
        __syncthreads();

        // convert W stg fp32 -> BHI fp16 swizzled
        {
            const char* stg = smem + STG_OFF + (ch % 3) * STG_SZ;
            char* bhi = smem + BHI_OFF + (ch & 1) * BHI_SZ;
#pragma unroll
            for (int i = 0; i < 4; i++) {
                int k = (tid >> 5) + i * 8;
                int nl = (tid & 31) * 4;
                float4 w4 = *(const float4*)(stg + k * 512 + nl * 4);
                uint32_t off = (uint32_t)(k * 256 + ((nl * 2) ^ ((k & 7) << 4)));
                uint2 hv;
                hv.x = pack_h2(w4.x, w4.y); hv.y = pack_h2(w4.z, w4.w);
                *(uint2*)(bhi + off) = hv;
            }
        }
        __syncthreads();

        if (ch + 2 < 16) issue_chunk32<MODE>(smem, sb, ch + 2, W, N, n0);

        // consume: 2 k-steps of 16
        const uint32_t abase = sb + AR_OFF + (ch % 3) * AR_SZ;
        const uint32_t bbase = sb + BHI_OFF + (ch & 1) * BHI_SZ;
#pragma unroll
        for (int ks = 0; ks < 2; ks++) {
            uint32_t bh[2][4];
#pragma unroll
            for (int nt = 0; nt < 2; nt++) {
                uint32_t boff = (uint32_t)((ks * 16 + (tt & 1) * 8 + lr) * 256 +
                                ((wn * 64 + nt * 32 + (tt >> 1) * 16) ^ swz));
                ldsm_x4_t(bh[nt], bbase + boff);
            }
#pragma unroll
            for (int mt = 0; mt < 4; mt++) {
                int row = wm * 64 + mt * 16 + (tt & 1) * 8 + lr;
                uint32_t aoff = (uint32_t)(row * 64 +
                                ((ks * 32 + (tt >> 1) * 16) ^ ((row & 3) << 4)));
                uint32_t ah[4], al[4];
                ldsm_x4(ah, abase + aoff);
                if (MODE == 1) ldsm_x4(al, abase + 8192 + aoff);
#pragma unroll
                for (int nt = 0; nt < 2; nt++) {
#pragma unroll
                    for (int f = 0; f < 2; f++) {
                        float* cc = c[mt][nt * 2 + f];
                        mma16816(cc, ah, &bh[nt][2 * f]);
                        if (MODE == 1) mma16816(cc, al, &bh[nt][2 * f]);
                    }
                }
            }
        }
        // ring reuse guarded by loop-top sync
    }
    __syncthreads();   // mainloop smem free

    // ---- epilogue: stage fp32 tile with bias ----
    float* sf = (float*)smem;
#pragma unroll
    for (int mt = 0; mt < 4; mt++) {
        int m = wm * 64 + mt * 16 + (lane >> 2);
#pragma unroll
        for (int nt = 0; nt < 4; nt++) {
            int nl = wn * 32 + nt * 8 + 2 * (lane & 3);
            int gn = n0 + nl;
            float b0 = (gn < N) ? __ldg(bias + gn) : 0.f;
            float b1 = (gn + 1 < N) ? __ldg(bias + gn + 1) : 0.f;
            *(float2*)(sf + m * SF_PITCH + nl) = make_float2(c[mt][nt][0] + b0, c[mt][nt][1] + b1);
            *(float2*)(sf + (m + 8) * SF_PITCH + nl) = make_float2(c[mt][nt][2] + b0, c[mt][nt][3] + b1);
        }
    }

    if (MODE == 1) {
        // load packed pairs (overlaps spin below)
        uint32_t* s_pair = (uint32_t*)(smem + PAIR_EPI);
#pragma unroll
        for (int g = 0; g < 4; g++) {
            int e4 = (g * 256 + tid) * 4;
            int gs = n0 * KDEG + e4;
            int4 i4 = make_int4(0, 0, 0, 0);
            float4 w4 = make_float4(0.f, 0.f, 0.f, 0.f);
            if (gs + 3 < S_ * KDEG) {
                i4 = *(const int4*)(sl_idx + gs);
                w4 = *(const float4*)(sl_w + gs);
            }
            s_pair[e4 + 0] = ((uint32_t)__half_as_ushort(__float2half_rn(w4.x)) << 16) | ((uint32_t)i4.x & 0xFFFF);
            s_pair[e4 + 1] = ((uint32_t)__half_as_ushort(__float2half_rn(w4.y)) << 16) | ((uint32_t)i4.y & 0xFFFF);
            s_pair[e4 + 2] = ((uint32_t)__half_as_ushort(__float2half_rn(w4.z)) << 16) | ((uint32_t)i4.z & 0xFFFF);
            s_pair[e4 + 3] = ((uint32_t)__half_as_ushort(__float2half_rn(w4.w)) << 16) | ((uint32_t)i4.w & 0xFFFF);
        }
        if (tid == 0) {
            int v;
            do {
                asm volatile("ld.global.acquire.gpu.s32 %0, [%1];" : "=r"(v) : "l"(&g_vdone));
                if (v < NVT) __nanosleep(64);
            } while (v < NVT);
        }
        __syncthreads();

        const int hh = lane >> 4;
        const int hl = lane & 15;
#pragma unroll
        for (int it = 0; it < 8; it++) {
            int sl = it * 16 + wid * 2 + hh;
            float acc[8];
#pragma unroll
            for (int j = 0; j < 8; j++) acc[j] = 0.f;
#pragma unroll 8
            for (int k = 0; k < KDEG; k++) {
                uint32_t p = s_pair[sl * KDEG + k];
                float wk = __half2float(__ushort_as_half((unsigned short)(p >> 16)));
                uint32_t jj = p & 0xFFFFu;
                uint4 raw = *(const uint4*)(g_vT + (size_t)jj * R_ + hl * 8);
                uint32_t rw[4] = {raw.x, raw.y, raw.z, raw.w};
#pragma unroll
                for (int q = 0; q < 4; q++) {
                    __half2 hp = *reinterpret_cast<__half2*>(&rw[q]);
                    float2 f = __half22float2(hp);
                    acc[2 * q + 0] = fmaf(wk, f.x, acc[2 * q + 0]);
                    acc[2 * q + 1] = fmaf(wk, f.y, acc[2 * q + 1]);
                }
            }
#pragma unroll
            for (int j = 0; j < 8; j++)
                sf[(hl * 8 + j) * SF_PITCH + sl] += SLM_SCALE * acc[j];
        }
        __syncthreads();
        float* out = outparam;
        for (int idx = tid; idx < 128 * 128; idx += 256) {
            int m = idx >> 7, n = idx & 127;
            int gn = n0 + n;
            if (gn < N) out[(size_t)m * N + gn] = sf[m * SF_PITCH + n];
        }
        __syncthreads();   // stores read sf before next tile's prologue reuses smem
    } else {
        __syncthreads();
        for (int idx = tid; idx < 128 * 64; idx += 256) {
            int n = idx >> 6, mp = idx & 63;
            int gn = n0 + n;
            if (gn < N) {
                float v0 = sf[(2 * mp) * SF_PITCH + n];
                float v1 = sf[(2 * mp + 1) * SF_PITCH + n];
                *(uint32_t*)((char*)g_vT + ((size_t)gn * R_ + 2 * mp) * 2) = pack_h2(v0, v1);
            }
        }
        __threadfence();
        __syncthreads();
        if (tid == 0) {
            int r;
            asm volatile("atom.global.release.gpu.add.s32 %0, [%1], 1;"
                         : "=r"(r) : "l"(&g_vdone) : "memory");
        }
    }
}

__global__ void __launch_bounds__(256, 2)
fat_persist(const float* __restrict__ Wslm, const float* __restrict__ bslm,
            const float* __restrict__ W2, const float* __restrict__ b2,
            float* __restrict__ out,
            const int* __restrict__ sl_idx, const float* __restrict__ sl_w) {
    for (int t = blockIdx.x; t < NTILES; t += PGRID) {
        if (t < NVT)
            tile_body<2>(Wslm, bslm, nullptr, V_, nullptr, nullptr, t);
        else
            tile_body<1>(W2, b2, out, S_, sl_idx, sl_w, t - NVT);
    }
}

// ============================================================
extern "C" void kernel_launch(void* const* d_in, const int* in_sizes, int n_in,
                              void* d_out, int out_size) {
    const float* x     = (const float*)d_in[0];
    const float* gamma = (const float*)d_in[1];
    const float* beta  = (const float*)d_in[2];
    const float* W1    = (const float*)d_in[3];
    const float* b1    = (const float*)d_in[4];
    const float* W2    = (const float*)d_in[5];
    const float* b2    = (const float*)d_in[6];
    const float* Wslm  = (const float*)d_in[7];
    const float* bslm  = (const float*)d_in[8];
    const float* slw   = (const float*)d_in[9];
    const int*   slidx = (const int*)d_in[10];
    float* out = (float*)d_out;

    cudaFuncSetAttribute(h_gemm, cudaFuncAttributeMaxDynamicSharedMemorySize, H_SMEM);
    cudaFuncSetAttribute(fat_persist, cudaFuncAttributeMaxDynamicSharedMemorySize, FAT_SMEM);

    bn_stats_kernel<<<L_, 256>>>(x, gamma, beta);
    h_gemm<<<H_ / 128, 256, H_SMEM>>>(W1, b1, x);
    fat_persist<<<PGRID, 256, FAT_SMEM>>>(Wslm, bslm, W2, b2, out, slidx, slw);
}